// round 4
// baseline (speedup 1.0000x reference)
#include <cuda_runtime.h>
#include <cuda_bf16.h>
#include <cstdint>

// ============================================================================
// Problem constants
// ============================================================================
#define GAMMA_F 0.00390625f

constexpr int B_ROWS = 65536;
constexpr int FEAT   = 256;
constexpr int S_DIM  = 1024;

// GEMM tiling: CTA 128x256, K-chunk 64, 8 warps of 64x64
constexpr int BM  = 128;
constexpr int BN  = 256;
constexpr int BK  = 64;
constexpr int NTH = 256;

// SMEM: rows padded 128B -> 144B (word stride ≡ 4 mod 32 => conflict-free frags)
constexpr int ROWB    = BK * 2 + 16;       // 144
constexpr int A_PLANE = BM * ROWB;         // 18432
constexpr int B_PLANE = BN * ROWB;         // 36864
constexpr int OFF_AH  = 0;
constexpr int OFF_AL  = A_PLANE;
constexpr int OFF_BH  = 2 * A_PLANE;
constexpr int OFF_BL  = 2 * A_PLANE + B_PLANE;
constexpr int STAGE   = 2 * A_PLANE + 2 * B_PLANE;   // 110592
constexpr int SMEM_TOTAL = 2 * STAGE;                // 221184 (<= 227 KB)

// ============================================================================
// Device scratch (__device__ globals: alloc-free rule)
// ============================================================================
__device__ __align__(16) __nv_bfloat16 g_xh[(size_t)B_ROWS * FEAT];
__device__ __align__(16) __nv_bfloat16 g_xl[(size_t)B_ROWS * FEAT];
__device__ __align__(16) __nv_bfloat16 g_svh[(size_t)S_DIM * FEAT];
__device__ __align__(16) __nv_bfloat16 g_svl[(size_t)S_DIM * FEAT];
__device__ __align__(16) __nv_bfloat16 g_w1h[(size_t)S_DIM * S_DIM];
__device__ __align__(16) __nv_bfloat16 g_w1l[(size_t)S_DIM * S_DIM];
__device__ __align__(16) __nv_bfloat16 g_w2h[(size_t)S_DIM * S_DIM];
__device__ __align__(16) __nv_bfloat16 g_w2l[(size_t)S_DIM * S_DIM];
__device__ __align__(16) __nv_bfloat16 g_kh[(size_t)B_ROWS * S_DIM];
__device__ __align__(16) __nv_bfloat16 g_kl[(size_t)B_ROWS * S_DIM];
__device__ __align__(16) __nv_bfloat16 g_hh[(size_t)B_ROWS * S_DIM];
__device__ __align__(16) __nv_bfloat16 g_hl[(size_t)B_ROWS * S_DIM];
__device__ float g_x2[B_ROWS];
__device__ float g_s2[S_DIM];
__device__ float g_part[16 * B_ROWS * 2];   // head partials [slot][row][2]

// ============================================================================
// PTX helpers (sm_100 baseline only: cp.async + mma.sync)
// ============================================================================
__device__ __forceinline__ uint32_t smem_u32(const void* p) {
    uint32_t a;
    asm("{ .reg .u64 t; cvta.to.shared.u64 t, %1; cvt.u32.u64 %0, t; }"
        : "=r"(a) : "l"(p));
    return a;
}

__device__ __forceinline__ void cp16(uint32_t s, const void* g) {
    asm volatile("cp.async.cg.shared.global [%0], [%1], 16;"
                 :: "r"(s), "l"((unsigned long long)(uintptr_t)g) : "memory");
}
#define CP_COMMIT()  asm volatile("cp.async.commit_group;" ::: "memory")
#define CP_WAIT(N)   asm volatile("cp.async.wait_group %0;" :: "n"(N) : "memory")

// mma.sync m16n8k16 row.col bf16 -> f32 (sm_80+ baseline)
#define MMA(C, A, Bv)                                                          \
    asm volatile(                                                              \
        "mma.sync.aligned.m16n8k16.row.col.f32.bf16.bf16.f32 "                 \
        "{%0,%1,%2,%3}, {%4,%5,%6,%7}, {%8,%9}, {%0,%1,%2,%3};"                \
        : "+f"((C)[0]), "+f"((C)[1]), "+f"((C)[2]), "+f"((C)[3])               \
        : "r"((A)[0]), "r"((A)[1]), "r"((A)[2]), "r"((A)[3]),                  \
          "r"((Bv)[0]), "r"((Bv)[1]))

// fp32 pair -> hi/lo bf16 planes
__device__ __forceinline__ void split2(float v0, float v1,
                                       __nv_bfloat162& h, __nv_bfloat162& l) {
    h = __floats2bfloat162_rn(v0, v1);
    float2 f = __bfloat1622float2(h);
    l = __floats2bfloat162_rn(v0 - f.x, v1 - f.y);
}

// ============================================================================
// Fused GEMM (bf16x2 3-term).  D[m,n] = sum_k A[m,k] * B[n,k]
//  EPI 0: k = exp(g*(2*dot - x2 - s2)) -> g_kh/g_kl
//  EPI 1: h = relu(dot + b1)           -> g_hh/g_hl
//  EPI 2: v = relu(dot + b2); head partials (v @ Wh^T) -> g_part
// ============================================================================
template <int KTOT, int EPI>
__global__ void __launch_bounds__(NTH, 1)
gemm_hmma(const __nv_bfloat16* __restrict__ Ah, const __nv_bfloat16* __restrict__ Al,
          const __nv_bfloat16* __restrict__ Bh, const __nv_bfloat16* __restrict__ Bl,
          const float* __restrict__ bias, const float* __restrict__ Wh) {
    extern __shared__ char smem[];
    const uint32_t sb0 = smem_u32(smem);

    const int tid    = threadIdx.x;
    const int wid    = tid >> 5;
    const int lane   = tid & 31;
    const int g      = lane >> 2;       // group 0..7
    const int tg     = lane & 3;        // thread-in-group 0..3
    const int warp_m = wid & 1;         // 0..1  (64-row halves)
    const int warp_n = wid >> 1;        // 0..3  (64-col quarters)

    const int rowBase = blockIdx.y * BM;
    const int colBase = blockIdx.x * BN;
    constexpr int NCHUNK = KTOT / BK;

    // ---- stage loader (all 256 threads) ----
    auto load_stage = [&](int c) {
        uint32_t s0 = sb0 + (c & 1) * STAGE;
        const int kc = c * BK;
        #pragma unroll
        for (int u = tid; u < BM * 8; u += NTH) {          // A: 128 rows x 8 chunks
            int row = u >> 3, seg = u & 7;
            size_t go = (size_t)(rowBase + row) * KTOT + kc + seg * 8;
            cp16(s0 + OFF_AH + row * ROWB + seg * 16, Ah + go);
            cp16(s0 + OFF_AL + row * ROWB + seg * 16, Al + go);
        }
        #pragma unroll
        for (int u = tid; u < BN * 8; u += NTH) {          // B: 256 rows x 8 chunks
            int row = u >> 3, seg = u & 7;
            size_t go = (size_t)(colBase + row) * KTOT + kc + seg * 8;
            cp16(s0 + OFF_BH + row * ROWB + seg * 16, Bh + go);
            cp16(s0 + OFF_BL + row * ROWB + seg * 16, Bl + go);
        }
        CP_COMMIT();
    };

    float acc[4][8][4];
    #pragma unroll
    for (int mt = 0; mt < 4; ++mt)
        #pragma unroll
        for (int nt = 0; nt < 8; ++nt)
            #pragma unroll
            for (int i = 0; i < 4; ++i) acc[mt][nt][i] = 0.f;

    load_stage(0);

    for (int c = 0; c < NCHUNK; ++c) {
        if (c + 1 < NCHUNK) { load_stage(c + 1); CP_WAIT(1); }
        else                { CP_WAIT(0); }
        __syncthreads();

        const char* sb = smem + (c & 1) * STAGE;

        #pragma unroll
        for (int kk = 0; kk < BK / 16; ++kk) {
            uint32_t aH[4][4], aL[4][4], bH[8][2], bL[8][2];
            #pragma unroll
            for (int mt = 0; mt < 4; ++mt) {
                uint32_t off = (uint32_t)((warp_m * 64 + mt * 16 + g) * ROWB + kk * 32 + tg * 4);
                aH[mt][0] = *(const uint32_t*)(sb + OFF_AH + off);
                aH[mt][1] = *(const uint32_t*)(sb + OFF_AH + off + 8 * ROWB);
                aH[mt][2] = *(const uint32_t*)(sb + OFF_AH + off + 16);
                aH[mt][3] = *(const uint32_t*)(sb + OFF_AH + off + 8 * ROWB + 16);
                aL[mt][0] = *(const uint32_t*)(sb + OFF_AL + off);
                aL[mt][1] = *(const uint32_t*)(sb + OFF_AL + off + 8 * ROWB);
                aL[mt][2] = *(const uint32_t*)(sb + OFF_AL + off + 16);
                aL[mt][3] = *(const uint32_t*)(sb + OFF_AL + off + 8 * ROWB + 16);
            }
            #pragma unroll
            for (int nt = 0; nt < 8; ++nt) {
                uint32_t off = (uint32_t)((warp_n * 64 + nt * 8 + g) * ROWB + kk * 32 + tg * 4);
                bH[nt][0] = *(const uint32_t*)(sb + OFF_BH + off);
                bH[nt][1] = *(const uint32_t*)(sb + OFF_BH + off + 16);
                bL[nt][0] = *(const uint32_t*)(sb + OFF_BL + off);
                bL[nt][1] = *(const uint32_t*)(sb + OFF_BL + off + 16);
            }
            #pragma unroll
            for (int mt = 0; mt < 4; ++mt)
                #pragma unroll
                for (int nt = 0; nt < 8; ++nt) {
                    MMA(acc[mt][nt], aH[mt], bH[nt]);   // hi*hi
                    MMA(acc[mt][nt], aH[mt], bL[nt]);   // hi*lo
                    MMA(acc[mt][nt], aL[mt], bH[nt]);   // lo*hi
                }
        }
        __syncthreads();   // protect buffer before next-next issue
    }

    // ---------------- Epilogue ----------------
    if constexpr (EPI == 0 || EPI == 1) {
        __nv_bfloat16* Dh = (EPI == 0) ? g_kh : g_hh;
        __nv_bfloat16* Dl = (EPI == 0) ? g_kl : g_hl;
        #pragma unroll
        for (int mt = 0; mt < 4; ++mt) {
            int r0 = rowBase + warp_m * 64 + mt * 16 + g;
            float x0 = 0.f, x1 = 0.f;
            if (EPI == 0) { x0 = g_x2[r0]; x1 = g_x2[r0 + 8]; }
            #pragma unroll
            for (int nt = 0; nt < 8; ++nt) {
                int cidx = colBase + warp_n * 64 + nt * 8 + 2 * tg;
                float v00, v01, v10, v11;
                if (EPI == 0) {
                    float s0v = g_s2[cidx], s1v = g_s2[cidx + 1];
                    v00 = __expf(GAMMA_F * (2.f * acc[mt][nt][0] - x0 - s0v));
                    v01 = __expf(GAMMA_F * (2.f * acc[mt][nt][1] - x0 - s1v));
                    v10 = __expf(GAMMA_F * (2.f * acc[mt][nt][2] - x1 - s0v));
                    v11 = __expf(GAMMA_F * (2.f * acc[mt][nt][3] - x1 - s1v));
                } else {
                    float b0v = bias[cidx], b1v = bias[cidx + 1];
                    v00 = fmaxf(acc[mt][nt][0] + b0v, 0.f);
                    v01 = fmaxf(acc[mt][nt][1] + b1v, 0.f);
                    v10 = fmaxf(acc[mt][nt][2] + b0v, 0.f);
                    v11 = fmaxf(acc[mt][nt][3] + b1v, 0.f);
                }
                __nv_bfloat162 h, l;
                size_t o0 = (size_t)r0 * S_DIM + cidx;
                size_t o1 = (size_t)(r0 + 8) * S_DIM + cidx;
                split2(v00, v01, h, l);
                *(__nv_bfloat162*)(Dh + o0) = h; *(__nv_bfloat162*)(Dl + o0) = l;
                split2(v10, v11, h, l);
                *(__nv_bfloat162*)(Dh + o1) = h; *(__nv_bfloat162*)(Dl + o1) = l;
            }
        }
    } else {
        // EPI 2: relu(acc + b2) then 2-logit head, reduced over cols
        float o0s[4][2], o1s[4][2];
        #pragma unroll
        for (int mt = 0; mt < 4; ++mt) { o0s[mt][0] = o0s[mt][1] = 0.f;
                                         o1s[mt][0] = o1s[mt][1] = 0.f; }
        #pragma unroll
        for (int nt = 0; nt < 8; ++nt) {
            int cidx = colBase + warp_n * 64 + nt * 8 + 2 * tg;
            float b0v = bias[cidx], b1v = bias[cidx + 1];
            float w00 = Wh[cidx],         w01 = Wh[cidx + 1];
            float w10 = Wh[S_DIM + cidx], w11 = Wh[S_DIM + cidx + 1];
            #pragma unroll
            for (int mt = 0; mt < 4; ++mt) {
                float v00 = fmaxf(acc[mt][nt][0] + b0v, 0.f);
                float v01 = fmaxf(acc[mt][nt][1] + b1v, 0.f);
                float v10 = fmaxf(acc[mt][nt][2] + b0v, 0.f);
                float v11 = fmaxf(acc[mt][nt][3] + b1v, 0.f);
                o0s[mt][0] = fmaf(v00, w00, fmaf(v01, w01, o0s[mt][0]));
                o1s[mt][0] = fmaf(v00, w10, fmaf(v01, w11, o1s[mt][0]));
                o0s[mt][1] = fmaf(v10, w00, fmaf(v11, w01, o0s[mt][1]));
                o1s[mt][1] = fmaf(v10, w10, fmaf(v11, w11, o1s[mt][1]));
            }
        }
        // reduce across tg (lanes xor 1, 2)
        #pragma unroll
        for (int mt = 0; mt < 4; ++mt)
            #pragma unroll
            for (int rh = 0; rh < 2; ++rh) {
                float a = o0s[mt][rh], b = o1s[mt][rh];
                a += __shfl_xor_sync(0xffffffffu, a, 1);
                a += __shfl_xor_sync(0xffffffffu, a, 2);
                b += __shfl_xor_sync(0xffffffffu, b, 1);
                b += __shfl_xor_sync(0xffffffffu, b, 2);
                o0s[mt][rh] = a; o1s[mt][rh] = b;
            }
        if (tg == 0) {
            int slot = blockIdx.x * 4 + warp_n;   // 0..15
            #pragma unroll
            for (int mt = 0; mt < 4; ++mt)
                #pragma unroll
                for (int rh = 0; rh < 2; ++rh) {
                    int row = rowBase + warp_m * 64 + mt * 16 + g + rh * 8;
                    size_t base = ((size_t)slot * B_ROWS + row) * 2;
                    g_part[base]     = o0s[mt][rh];
                    g_part[base + 1] = o1s[mt][rh];
                }
        }
    }
}

// ============================================================================
// Small kernels
// ============================================================================
__global__ void split_kernel(const float* __restrict__ src,
                             __nv_bfloat16* __restrict__ hi,
                             __nv_bfloat16* __restrict__ lo, int n4) {
    int i = blockIdx.x * blockDim.x + threadIdx.x;
    if (i >= n4) return;
    float4 v = ((const float4*)src)[i];
    __nv_bfloat162 h01, l01, h23, l23;
    split2(v.x, v.y, h01, l01);
    split2(v.z, v.w, h23, l23);
    ((__nv_bfloat162*)hi)[2 * i]     = h01;
    ((__nv_bfloat162*)hi)[2 * i + 1] = h23;
    ((__nv_bfloat162*)lo)[2 * i]     = l01;
    ((__nv_bfloat162*)lo)[2 * i + 1] = l23;
}

__global__ void rownorm_kernel(const float* __restrict__ X, int rows, int cols, int which) {
    int row  = blockIdx.x * (blockDim.x >> 5) + (threadIdx.x >> 5);
    int lane = threadIdx.x & 31;
    if (row >= rows) return;
    float s = 0.f;
    for (int c = lane; c < cols; c += 32) {
        float v = X[(size_t)row * cols + c];
        s = fmaf(v, v, s);
    }
    #pragma unroll
    for (int o = 16; o; o >>= 1) s += __shfl_xor_sync(0xffffffffu, s, o);
    if (lane == 0) { if (which) g_s2[row] = s; else g_x2[row] = s; }
}

__global__ void head_final(const float* __restrict__ bh, float* __restrict__ out) {
    int i = blockIdx.x * blockDim.x + threadIdx.x;
    if (i < B_ROWS * 2) {
        float s = bh[i & 1];
        #pragma unroll
        for (int t = 0; t < 16; ++t) s += g_part[(size_t)t * B_ROWS * 2 + i];
        out[i] = s;
    }
}

// ============================================================================
// Launcher
// ============================================================================
extern "C" void kernel_launch(void* const* d_in, const int* in_sizes, int n_in,
                              void* d_out, int out_size) {
    (void)in_sizes; (void)n_in; (void)out_size;
    const float* x  = (const float*)d_in[0];
    const float* sv = (const float*)d_in[1];
    const float* W1 = (const float*)d_in[2];
    const float* b1 = (const float*)d_in[3];
    const float* W2 = (const float*)d_in[4];
    const float* b2 = (const float*)d_in[5];
    const float* Wh = (const float*)d_in[6];
    const float* bh = (const float*)d_in[7];
    float* out = (float*)d_out;

    static __nv_bfloat16 *xh, *xl, *svh, *svl, *w1h, *w1l, *w2h, *w2l,
                         *kh, *kl, *hh, *hl;
    static bool got = false;
    if (!got) {
        cudaGetSymbolAddress((void**)&xh,  g_xh);  cudaGetSymbolAddress((void**)&xl,  g_xl);
        cudaGetSymbolAddress((void**)&svh, g_svh); cudaGetSymbolAddress((void**)&svl, g_svl);
        cudaGetSymbolAddress((void**)&w1h, g_w1h); cudaGetSymbolAddress((void**)&w1l, g_w1l);
        cudaGetSymbolAddress((void**)&w2h, g_w2h); cudaGetSymbolAddress((void**)&w2l, g_w2l);
        cudaGetSymbolAddress((void**)&kh,  g_kh);  cudaGetSymbolAddress((void**)&kl,  g_kl);
        cudaGetSymbolAddress((void**)&hh,  g_hh);  cudaGetSymbolAddress((void**)&hl,  g_hl);
        cudaFuncSetAttribute((const void*)gemm_hmma<FEAT, 0>,
                             cudaFuncAttributeMaxDynamicSharedMemorySize, SMEM_TOTAL);
        cudaFuncSetAttribute((const void*)gemm_hmma<S_DIM, 1>,
                             cudaFuncAttributeMaxDynamicSharedMemorySize, SMEM_TOTAL);
        cudaFuncSetAttribute((const void*)gemm_hmma<S_DIM, 2>,
                             cudaFuncAttributeMaxDynamicSharedMemorySize, SMEM_TOTAL);
        got = true;
    }

    // pre-split fp32 -> hi/lo bf16 planes
    split_kernel<<<(B_ROWS * FEAT / 4 + 255) / 256, 256>>>(x,  xh,  xl,  B_ROWS * FEAT / 4);
    split_kernel<<<(S_DIM * FEAT / 4 + 255) / 256, 256>>>(sv, svh, svl, S_DIM * FEAT / 4);
    split_kernel<<<(S_DIM * S_DIM / 4 + 255) / 256, 256>>>(W1, w1h, w1l, S_DIM * S_DIM / 4);
    split_kernel<<<(S_DIM * S_DIM / 4 + 255) / 256, 256>>>(W2, w2h, w2l, S_DIM * S_DIM / 4);

    rownorm_kernel<<<B_ROWS / 8, 256>>>(x, B_ROWS, FEAT, 0);
    rownorm_kernel<<<S_DIM / 8, 256>>>(sv, S_DIM, FEAT, 1);

    dim3 grid(S_DIM / BN, B_ROWS / BM);   // (4, 512)
    gemm_hmma<FEAT, 0><<<grid, NTH, SMEM_TOTAL>>>(xh, xl, svh, svl, nullptr, nullptr);
    gemm_hmma<S_DIM, 1><<<grid, NTH, SMEM_TOTAL>>>(kh, kl, w1h, w1l, b1, nullptr);
    gemm_hmma<S_DIM, 2><<<grid, NTH, SMEM_TOTAL>>>(hh, hl, w2h, w2l, b2, Wh);

    head_final<<<(B_ROWS * 2 + 255) / 256, 256>>>(bh, out);
}

// round 5
// speedup vs baseline: 1.0153x; 1.0153x over previous
#include <cuda_runtime.h>
#include <cuda_bf16.h>
#include <cstdint>

// ============================================================================
// Problem constants
// ============================================================================
#define GAMMA_F 0.00390625f

constexpr int B_ROWS = 65536;
constexpr int FEAT   = 256;
constexpr int S_DIM  = 1024;

// GEMM tiling: CTA 128x256, K-chunk 64, 16 warps of 64x32
constexpr int BM  = 128;
constexpr int BN  = 256;
constexpr int BK  = 64;
constexpr int NTH = 512;

// SMEM rows padded 128B -> 144B (9 x 16B => ldmatrix rows hit 8 distinct groups)
constexpr int ROWB    = BK * 2 + 16;       // 144
constexpr int A_PLANE = BM * ROWB;         // 18432
constexpr int B_PLANE = BN * ROWB;         // 36864
constexpr int OFF_AH  = 0;
constexpr int OFF_AL  = A_PLANE;
constexpr int OFF_BH  = 2 * A_PLANE;
constexpr int OFF_BL  = 2 * A_PLANE + B_PLANE;
constexpr int STAGE   = 2 * A_PLANE + 2 * B_PLANE;   // 110592
constexpr int SMEM_TOTAL = 2 * STAGE;                // 221184

// ============================================================================
// Device scratch (__device__ globals: alloc-free rule)
// ============================================================================
__device__ __align__(16) __nv_bfloat16 g_xh[(size_t)B_ROWS * FEAT];
__device__ __align__(16) __nv_bfloat16 g_xl[(size_t)B_ROWS * FEAT];
__device__ __align__(16) __nv_bfloat16 g_svh[(size_t)S_DIM * FEAT];
__device__ __align__(16) __nv_bfloat16 g_svl[(size_t)S_DIM * FEAT];
__device__ __align__(16) __nv_bfloat16 g_w1h[(size_t)S_DIM * S_DIM];
__device__ __align__(16) __nv_bfloat16 g_w1l[(size_t)S_DIM * S_DIM];
__device__ __align__(16) __nv_bfloat16 g_w2h[(size_t)S_DIM * S_DIM];
__device__ __align__(16) __nv_bfloat16 g_w2l[(size_t)S_DIM * S_DIM];
__device__ __align__(16) __nv_bfloat16 g_kh[(size_t)B_ROWS * S_DIM];
__device__ __align__(16) __nv_bfloat16 g_kl[(size_t)B_ROWS * S_DIM];
__device__ __align__(16) __nv_bfloat16 g_hh[(size_t)B_ROWS * S_DIM];
__device__ __align__(16) __nv_bfloat16 g_hl[(size_t)B_ROWS * S_DIM];
__device__ float g_x2[B_ROWS];
__device__ float g_s2[S_DIM];
__device__ float g_part[32 * B_ROWS * 2];   // head partials [slot][row][2]

// ============================================================================
// PTX helpers (sm_100 baseline: cp.async + ldmatrix + mma.sync)
// ============================================================================
__device__ __forceinline__ uint32_t smem_u32(const void* p) {
    uint32_t a;
    asm("{ .reg .u64 t; cvta.to.shared.u64 t, %1; cvt.u32.u64 %0, t; }"
        : "=r"(a) : "l"(p));
    return a;
}

__device__ __forceinline__ void cp16(uint32_t s, const void* g) {
    asm volatile("cp.async.cg.shared.global [%0], [%1], 16;"
                 :: "r"(s), "l"((unsigned long long)(uintptr_t)g) : "memory");
}
#define CP_COMMIT()  asm volatile("cp.async.commit_group;" ::: "memory")
#define CP_WAIT0()   asm volatile("cp.async.wait_group 0;" ::: "memory")

__device__ __forceinline__ void ldm_x4(uint32_t* r, uint32_t saddr) {
    asm volatile("ldmatrix.sync.aligned.m8n8.x4.shared.b16 {%0,%1,%2,%3}, [%4];"
                 : "=r"(r[0]), "=r"(r[1]), "=r"(r[2]), "=r"(r[3]) : "r"(saddr));
}

// mma.sync m16n8k16 row.col bf16 -> f32
#define MMA(C, A, B0, B1)                                                      \
    asm volatile(                                                              \
        "mma.sync.aligned.m16n8k16.row.col.f32.bf16.bf16.f32 "                 \
        "{%0,%1,%2,%3}, {%4,%5,%6,%7}, {%8,%9}, {%0,%1,%2,%3};"                \
        : "+f"((C)[0]), "+f"((C)[1]), "+f"((C)[2]), "+f"((C)[3])               \
        : "r"((A)[0]), "r"((A)[1]), "r"((A)[2]), "r"((A)[3]),                  \
          "r"(B0), "r"(B1))

__device__ __forceinline__ void split2(float v0, float v1,
                                       __nv_bfloat162& h, __nv_bfloat162& l) {
    h = __floats2bfloat162_rn(v0, v1);
    float2 f = __bfloat1622float2(h);
    l = __floats2bfloat162_rn(v0 - f.x, v1 - f.y);
}

// ============================================================================
// Fused GEMM (bf16x2 3-term).  D[m,n] = sum_k A[m,k] * B[n,k]
//  EPI 0: k = exp(g*(2*dot - x2 - s2)) -> g_kh/g_kl
//  EPI 1: h = relu(dot + b1)           -> g_hh/g_hl
//  EPI 2: v = relu(dot + b2); head partials (v @ Wh^T) -> g_part
// ============================================================================
template <int KTOT, int EPI>
__global__ void __launch_bounds__(NTH, 1)
gemm_hmma(const __nv_bfloat16* __restrict__ Ah, const __nv_bfloat16* __restrict__ Al,
          const __nv_bfloat16* __restrict__ Bh, const __nv_bfloat16* __restrict__ Bl,
          const float* __restrict__ bias, const float* __restrict__ Wh) {
    extern __shared__ char smem[];
    const uint32_t sb0 = smem_u32(smem);

    const int tid    = threadIdx.x;
    const int wid    = tid >> 5;
    const int lane   = tid & 31;
    const int g      = lane >> 2;       // 0..7
    const int tg     = lane & 3;        // 0..3
    const int warp_m = wid & 1;         // 0..1  (64-row halves)
    const int warp_n = wid >> 1;        // 0..7  (32-col slices)

    const int rowBase = blockIdx.y * BM;
    const int colBase = blockIdx.x * BN;
    constexpr int NCHUNK = KTOT / BK;

    // ldmatrix lane-dependent address components
    // A x4: matrices {m0-7,k0-7} {m8-15,k0-7} {m0-7,k8-15} {m8-15,k8-15}
    const int a_row  = warp_m * 64 + (lane & 7) + ((lane >> 3) & 1) * 8;
    const int a_kby  = (lane >> 4) * 16;
    // B x4: matrices {n0-7,k0-7} {n0-7,k8-15} {n8-15,k0-7} {n8-15,k8-15}
    const int b_row  = warp_n * 32 + (lane & 7) + (lane >> 4) * 8;
    const int b_kby  = ((lane >> 3) & 1) * 16;

    // ---- stage loader (all 512 threads) ----
    auto load_stage = [&](int c) {
        uint32_t s0 = sb0 + (c & 1) * STAGE;
        const int kc = c * BK;
        #pragma unroll
        for (int u = tid; u < BM * 8; u += NTH) {
            int row = u >> 3, seg = u & 7;
            size_t go = (size_t)(rowBase + row) * KTOT + kc + seg * 8;
            cp16(s0 + OFF_AH + row * ROWB + seg * 16, Ah + go);
            cp16(s0 + OFF_AL + row * ROWB + seg * 16, Al + go);
        }
        #pragma unroll
        for (int u = tid; u < BN * 8; u += NTH) {
            int row = u >> 3, seg = u & 7;
            size_t go = (size_t)(colBase + row) * KTOT + kc + seg * 8;
            cp16(s0 + OFF_BH + row * ROWB + seg * 16, Bh + go);
            cp16(s0 + OFF_BL + row * ROWB + seg * 16, Bl + go);
        }
        CP_COMMIT();
    };

    float acc[4][4][4];
    #pragma unroll
    for (int mt = 0; mt < 4; ++mt)
        #pragma unroll
        for (int nt = 0; nt < 4; ++nt)
            #pragma unroll
            for (int i = 0; i < 4; ++i) acc[mt][nt][i] = 0.f;

    load_stage(0);

    for (int c = 0; c < NCHUNK; ++c) {
        CP_WAIT0();           // own-thread loads of stage c complete
        __syncthreads();      // whole stage c visible; stage (c+1)&1 free
        if (c + 1 < NCHUNK) load_stage(c + 1);   // overlaps compute below

        const uint32_t sb = sb0 + (c & 1) * STAGE;

        #pragma unroll
        for (int kk = 0; kk < BK / 16; ++kk) {
            uint32_t aH[4][4], aL[4][4], bH[2][4], bL[2][4];
            #pragma unroll
            for (int mt = 0; mt < 4; ++mt) {
                uint32_t ao = sb + (uint32_t)((a_row + mt * 16) * ROWB + kk * 32 + a_kby);
                ldm_x4(aH[mt], ao + OFF_AH);
                ldm_x4(aL[mt], ao + OFF_AL);
            }
            #pragma unroll
            for (int ne = 0; ne < 2; ++ne) {
                uint32_t bo = sb + (uint32_t)((b_row + ne * 16) * ROWB + kk * 32 + b_kby);
                ldm_x4(bH[ne], bo + OFF_BH);
                ldm_x4(bL[ne], bo + OFF_BL);
            }
            #pragma unroll
            for (int mt = 0; mt < 4; ++mt)
                #pragma unroll
                for (int nt = 0; nt < 4; ++nt) {
                    const int ne = nt >> 1, h2 = (nt & 1) * 2;
                    MMA(acc[mt][nt], aH[mt], bH[ne][h2], bH[ne][h2 + 1]); // hi*hi
                    MMA(acc[mt][nt], aH[mt], bL[ne][h2], bL[ne][h2 + 1]); // hi*lo
                    MMA(acc[mt][nt], aL[mt], bH[ne][h2], bH[ne][h2 + 1]); // lo*hi
                }
        }
        __syncthreads();      // all reads of stage c done before next overwrite cycle
    }

    // ---------------- Epilogue ----------------
    if constexpr (EPI == 0 || EPI == 1) {
        __nv_bfloat16* Dh = (EPI == 0) ? g_kh : g_hh;
        __nv_bfloat16* Dl = (EPI == 0) ? g_kl : g_hl;
        #pragma unroll
        for (int mt = 0; mt < 4; ++mt) {
            int r0 = rowBase + warp_m * 64 + mt * 16 + g;
            float x0 = 0.f, x1 = 0.f;
            if (EPI == 0) { x0 = g_x2[r0]; x1 = g_x2[r0 + 8]; }
            #pragma unroll
            for (int nt = 0; nt < 4; ++nt) {
                int cidx = colBase + warp_n * 32 + nt * 8 + 2 * tg;
                float v00, v01, v10, v11;
                if (EPI == 0) {
                    float s0v = g_s2[cidx], s1v = g_s2[cidx + 1];
                    v00 = __expf(GAMMA_F * (2.f * acc[mt][nt][0] - x0 - s0v));
                    v01 = __expf(GAMMA_F * (2.f * acc[mt][nt][1] - x0 - s1v));
                    v10 = __expf(GAMMA_F * (2.f * acc[mt][nt][2] - x1 - s0v));
                    v11 = __expf(GAMMA_F * (2.f * acc[mt][nt][3] - x1 - s1v));
                } else {
                    float b0v = bias[cidx], b1v = bias[cidx + 1];
                    v00 = fmaxf(acc[mt][nt][0] + b0v, 0.f);
                    v01 = fmaxf(acc[mt][nt][1] + b1v, 0.f);
                    v10 = fmaxf(acc[mt][nt][2] + b0v, 0.f);
                    v11 = fmaxf(acc[mt][nt][3] + b1v, 0.f);
                }
                __nv_bfloat162 h, l;
                size_t o0 = (size_t)r0 * S_DIM + cidx;
                size_t o1 = (size_t)(r0 + 8) * S_DIM + cidx;
                split2(v00, v01, h, l);
                *(__nv_bfloat162*)(Dh + o0) = h; *(__nv_bfloat162*)(Dl + o0) = l;
                split2(v10, v11, h, l);
                *(__nv_bfloat162*)(Dh + o1) = h; *(__nv_bfloat162*)(Dl + o1) = l;
            }
        }
    } else {
        float o0s[4][2], o1s[4][2];
        #pragma unroll
        for (int mt = 0; mt < 4; ++mt) { o0s[mt][0] = o0s[mt][1] = 0.f;
                                         o1s[mt][0] = o1s[mt][1] = 0.f; }
        #pragma unroll
        for (int nt = 0; nt < 4; ++nt) {
            int cidx = colBase + warp_n * 32 + nt * 8 + 2 * tg;
            float b0v = bias[cidx], b1v = bias[cidx + 1];
            float w00 = Wh[cidx],         w01 = Wh[cidx + 1];
            float w10 = Wh[S_DIM + cidx], w11 = Wh[S_DIM + cidx + 1];
            #pragma unroll
            for (int mt = 0; mt < 4; ++mt) {
                float v00 = fmaxf(acc[mt][nt][0] + b0v, 0.f);
                float v01 = fmaxf(acc[mt][nt][1] + b1v, 0.f);
                float v10 = fmaxf(acc[mt][nt][2] + b0v, 0.f);
                float v11 = fmaxf(acc[mt][nt][3] + b1v, 0.f);
                o0s[mt][0] = fmaf(v00, w00, fmaf(v01, w01, o0s[mt][0]));
                o1s[mt][0] = fmaf(v00, w10, fmaf(v01, w11, o1s[mt][0]));
                o0s[mt][1] = fmaf(v10, w00, fmaf(v11, w01, o0s[mt][1]));
                o1s[mt][1] = fmaf(v10, w10, fmaf(v11, w11, o1s[mt][1]));
            }
        }
        #pragma unroll
        for (int mt = 0; mt < 4; ++mt)
            #pragma unroll
            for (int rh = 0; rh < 2; ++rh) {
                float a = o0s[mt][rh], b = o1s[mt][rh];
                a += __shfl_xor_sync(0xffffffffu, a, 1);
                a += __shfl_xor_sync(0xffffffffu, a, 2);
                b += __shfl_xor_sync(0xffffffffu, b, 1);
                b += __shfl_xor_sync(0xffffffffu, b, 2);
                o0s[mt][rh] = a; o1s[mt][rh] = b;
            }
        if (tg == 0) {
            int slot = blockIdx.x * 8 + warp_n;   // 0..31
            #pragma unroll
            for (int mt = 0; mt < 4; ++mt)
                #pragma unroll
                for (int rh = 0; rh < 2; ++rh) {
                    int row = rowBase + warp_m * 64 + mt * 16 + g + rh * 8;
                    size_t base = ((size_t)slot * B_ROWS + row) * 2;
                    g_part[base]     = o0s[mt][rh];
                    g_part[base + 1] = o1s[mt][rh];
                }
        }
    }
}

// ============================================================================
// Small kernels
// ============================================================================
__global__ void split_kernel(const float* __restrict__ src,
                             __nv_bfloat16* __restrict__ hi,
                             __nv_bfloat16* __restrict__ lo, int n4) {
    int i = blockIdx.x * blockDim.x + threadIdx.x;
    if (i >= n4) return;
    float4 v = ((const float4*)src)[i];
    __nv_bfloat162 h01, l01, h23, l23;
    split2(v.x, v.y, h01, l01);
    split2(v.z, v.w, h23, l23);
    ((__nv_bfloat162*)hi)[2 * i]     = h01;
    ((__nv_bfloat162*)hi)[2 * i + 1] = h23;
    ((__nv_bfloat162*)lo)[2 * i]     = l01;
    ((__nv_bfloat162*)lo)[2 * i + 1] = l23;
}

__global__ void rownorm_kernel(const float* __restrict__ X, int rows, int cols, int which) {
    int row  = blockIdx.x * (blockDim.x >> 5) + (threadIdx.x >> 5);
    int lane = threadIdx.x & 31;
    if (row >= rows) return;
    float s = 0.f;
    for (int c = lane; c < cols; c += 32) {
        float v = X[(size_t)row * cols + c];
        s = fmaf(v, v, s);
    }
    #pragma unroll
    for (int o = 16; o; o >>= 1) s += __shfl_xor_sync(0xffffffffu, s, o);
    if (lane == 0) { if (which) g_s2[row] = s; else g_x2[row] = s; }
}

__global__ void head_final(const float* __restrict__ bh, float* __restrict__ out) {
    int i = blockIdx.x * blockDim.x + threadIdx.x;
    if (i < B_ROWS * 2) {
        float s = bh[i & 1];
        #pragma unroll
        for (int t = 0; t < 32; ++t) s += g_part[(size_t)t * B_ROWS * 2 + i];
        out[i] = s;
    }
}

// ============================================================================
// Launcher
// ============================================================================
extern "C" void kernel_launch(void* const* d_in, const int* in_sizes, int n_in,
                              void* d_out, int out_size) {
    (void)in_sizes; (void)n_in; (void)out_size;
    const float* x  = (const float*)d_in[0];
    const float* sv = (const float*)d_in[1];
    const float* W1 = (const float*)d_in[2];
    const float* b1 = (const float*)d_in[3];
    const float* W2 = (const float*)d_in[4];
    const float* b2 = (const float*)d_in[5];
    const float* Wh = (const float*)d_in[6];
    const float* bh = (const float*)d_in[7];
    float* out = (float*)d_out;

    static __nv_bfloat16 *xh, *xl, *svh, *svl, *w1h, *w1l, *w2h, *w2l,
                         *kh, *kl, *hh, *hl;
    static bool got = false;
    if (!got) {
        cudaGetSymbolAddress((void**)&xh,  g_xh);  cudaGetSymbolAddress((void**)&xl,  g_xl);
        cudaGetSymbolAddress((void**)&svh, g_svh); cudaGetSymbolAddress((void**)&svl, g_svl);
        cudaGetSymbolAddress((void**)&w1h, g_w1h); cudaGetSymbolAddress((void**)&w1l, g_w1l);
        cudaGetSymbolAddress((void**)&w2h, g_w2h); cudaGetSymbolAddress((void**)&w2l, g_w2l);
        cudaGetSymbolAddress((void**)&kh,  g_kh);  cudaGetSymbolAddress((void**)&kl,  g_kl);
        cudaGetSymbolAddress((void**)&hh,  g_hh);  cudaGetSymbolAddress((void**)&hl,  g_hl);
        cudaFuncSetAttribute((const void*)gemm_hmma<FEAT, 0>,
                             cudaFuncAttributeMaxDynamicSharedMemorySize, SMEM_TOTAL);
        cudaFuncSetAttribute((const void*)gemm_hmma<S_DIM, 1>,
                             cudaFuncAttributeMaxDynamicSharedMemorySize, SMEM_TOTAL);
        cudaFuncSetAttribute((const void*)gemm_hmma<S_DIM, 2>,
                             cudaFuncAttributeMaxDynamicSharedMemorySize, SMEM_TOTAL);
        got = true;
    }

    split_kernel<<<(B_ROWS * FEAT / 4 + 255) / 256, 256>>>(x,  xh,  xl,  B_ROWS * FEAT / 4);
    split_kernel<<<(S_DIM * FEAT / 4 + 255) / 256, 256>>>(sv, svh, svl, S_DIM * FEAT / 4);
    split_kernel<<<(S_DIM * S_DIM / 4 + 255) / 256, 256>>>(W1, w1h, w1l, S_DIM * S_DIM / 4);
    split_kernel<<<(S_DIM * S_DIM / 4 + 255) / 256, 256>>>(W2, w2h, w2l, S_DIM * S_DIM / 4);

    rownorm_kernel<<<B_ROWS / 8, 256>>>(x, B_ROWS, FEAT, 0);
    rownorm_kernel<<<S_DIM / 8, 256>>>(sv, S_DIM, FEAT, 1);

    dim3 grid(S_DIM / BN, B_ROWS / BM);   // (4, 512)
    gemm_hmma<FEAT, 0><<<grid, NTH, SMEM_TOTAL>>>(xh, xl, svh, svl, nullptr, nullptr);
    gemm_hmma<S_DIM, 1><<<grid, NTH, SMEM_TOTAL>>>(kh, kl, w1h, w1l, b1, nullptr);
    gemm_hmma<S_DIM, 2><<<grid, NTH, SMEM_TOTAL>>>(hh, hl, w2h, w2l, b2, Wh);

    head_final<<<(B_ROWS * 2 + 255) / 256, 256>>>(bh, out);
}

// round 6
// speedup vs baseline: 1.0215x; 1.0062x over previous
#include <cuda_runtime.h>
#include <cuda_bf16.h>
#include <cstdint>

// ============================================================================
// Problem constants
// ============================================================================
#define GAMMA_F 0.00390625f

constexpr int B_ROWS = 65536;
constexpr int FEAT   = 256;
constexpr int S_DIM  = 1024;

// GEMM tiling: CTA 128x256, K-chunk 64, 16 warps of 64x32
constexpr int BM  = 128;
constexpr int BN  = 256;
constexpr int BK  = 64;
constexpr int NTH = 512;

// SMEM rows padded 128B -> 144B
constexpr int ROWB    = BK * 2 + 16;       // 144
constexpr int A_PLANE = BM * ROWB;         // 18432
constexpr int B_PLANE = BN * ROWB;         // 36864
constexpr int OFF_AH  = 0;
constexpr int OFF_AL  = A_PLANE;
constexpr int OFF_BH  = 2 * A_PLANE;
constexpr int OFF_BL  = 2 * A_PLANE + B_PLANE;
constexpr int STAGE   = 2 * A_PLANE + 2 * B_PLANE;   // 110592
constexpr int SMEM_TOTAL = 2 * STAGE;                // 221184

// ============================================================================
// Device scratch (__device__ globals: alloc-free rule)
// ============================================================================
__device__ __align__(16) __nv_bfloat16 g_xh[(size_t)B_ROWS * FEAT];
__device__ __align__(16) __nv_bfloat16 g_xl[(size_t)B_ROWS * FEAT];
__device__ __align__(16) __nv_bfloat16 g_svh[(size_t)S_DIM * FEAT];
__device__ __align__(16) __nv_bfloat16 g_svl[(size_t)S_DIM * FEAT];
__device__ __align__(16) __nv_bfloat16 g_w1h[(size_t)S_DIM * S_DIM];
__device__ __align__(16) __nv_bfloat16 g_w1l[(size_t)S_DIM * S_DIM];
__device__ __align__(16) __nv_bfloat16 g_w2h[(size_t)S_DIM * S_DIM];
__device__ __align__(16) __nv_bfloat16 g_w2l[(size_t)S_DIM * S_DIM];
__device__ __align__(16) __nv_bfloat16 g_kh[(size_t)B_ROWS * S_DIM];
__device__ __align__(16) __nv_bfloat16 g_kl[(size_t)B_ROWS * S_DIM];
__device__ __align__(16) __nv_bfloat16 g_hh[(size_t)B_ROWS * S_DIM];
__device__ __align__(16) __nv_bfloat16 g_hl[(size_t)B_ROWS * S_DIM];
__device__ float g_x2[B_ROWS];
__device__ float g_s2[S_DIM];
__device__ float g_part[32 * B_ROWS * 2];   // head partials [slot][row][2]

// ============================================================================
// PTX helpers (sm_100 baseline: cp.async + ldmatrix + mma.sync)
// ============================================================================
__device__ __forceinline__ uint32_t smem_u32(const void* p) {
    uint32_t a;
    asm("{ .reg .u64 t; cvta.to.shared.u64 t, %1; cvt.u32.u64 %0, t; }"
        : "=r"(a) : "l"(p));
    return a;
}

__device__ __forceinline__ void cp16(uint32_t s, const void* g) {
    asm volatile("cp.async.cg.shared.global [%0], [%1], 16;"
                 :: "r"(s), "l"((unsigned long long)(uintptr_t)g) : "memory");
}
#define CP_COMMIT()  asm volatile("cp.async.commit_group;" ::: "memory")
#define CP_WAIT0()   asm volatile("cp.async.wait_group 0;" ::: "memory")

__device__ __forceinline__ void ldm_x4(uint32_t* r, uint32_t saddr) {
    asm volatile("ldmatrix.sync.aligned.m8n8.x4.shared.b16 {%0,%1,%2,%3}, [%4];"
                 : "=r"(r[0]), "=r"(r[1]), "=r"(r[2]), "=r"(r[3]) : "r"(saddr));
}

// mma.sync m16n8k16 row.col bf16 -> f32
#define MMA(C, A, B0, B1)                                                      \
    asm volatile(                                                              \
        "mma.sync.aligned.m16n8k16.row.col.f32.bf16.bf16.f32 "                 \
        "{%0,%1,%2,%3}, {%4,%5,%6,%7}, {%8,%9}, {%0,%1,%2,%3};"                \
        : "+f"((C)[0]), "+f"((C)[1]), "+f"((C)[2]), "+f"((C)[3])               \
        : "r"((A)[0]), "r"((A)[1]), "r"((A)[2]), "r"((A)[3]),                  \
          "r"(B0), "r"(B1))

__device__ __forceinline__ void split2(float v0, float v1,
                                       __nv_bfloat162& h, __nv_bfloat162& l) {
    h = __floats2bfloat162_rn(v0, v1);
    float2 f = __bfloat1622float2(h);
    l = __floats2bfloat162_rn(v0 - f.x, v1 - f.y);
}

// ============================================================================
// Fused GEMM (bf16x2 3-term, term-major MMA order).
//  D[m,n] = sum_k A[m,k] * B[n,k]
//  EPI 0: k = exp(g*(2*dot - x2 - s2)) -> g_kh/g_kl
//  EPI 1: h = relu(dot + b1)           -> g_hh/g_hl
//  EPI 2: v = relu(dot + b2); head partials (v @ Wh^T) -> g_part
// ============================================================================
template <int KTOT, int EPI>
__global__ void __launch_bounds__(NTH, 1)
gemm_hmma(const __nv_bfloat16* __restrict__ Ah, const __nv_bfloat16* __restrict__ Al,
          const __nv_bfloat16* __restrict__ Bh, const __nv_bfloat16* __restrict__ Bl,
          const float* __restrict__ bias, const float* __restrict__ Wh) {
    extern __shared__ char smem[];
    const uint32_t sb0 = smem_u32(smem);

    const int tid    = threadIdx.x;
    const int wid    = tid >> 5;
    const int lane   = tid & 31;
    const int g      = lane >> 2;
    const int tg     = lane & 3;
    const int warp_m = wid & 1;         // 0..1  (64-row halves)
    const int warp_n = wid >> 1;        // 0..7  (32-col slices)

    const int rowBase = blockIdx.y * BM;
    const int colBase = blockIdx.x * BN;
    constexpr int NCHUNK = KTOT / BK;

    // ldmatrix lane-dependent address components
    const int a_row  = warp_m * 64 + (lane & 7) + ((lane >> 3) & 1) * 8;
    const int a_kby  = (lane >> 4) * 16;
    const int b_row  = warp_n * 32 + (lane & 7) + (lane >> 4) * 8;
    const int b_kby  = ((lane >> 3) & 1) * 16;

    auto load_stage = [&](int c) {
        uint32_t s0 = sb0 + (c & 1) * STAGE;
        const int kc = c * BK;
        #pragma unroll
        for (int u = tid; u < BM * 8; u += NTH) {
            int row = u >> 3, seg = u & 7;
            size_t go = (size_t)(rowBase + row) * KTOT + kc + seg * 8;
            cp16(s0 + OFF_AH + row * ROWB + seg * 16, Ah + go);
            cp16(s0 + OFF_AL + row * ROWB + seg * 16, Al + go);
        }
        #pragma unroll
        for (int u = tid; u < BN * 8; u += NTH) {
            int row = u >> 3, seg = u & 7;
            size_t go = (size_t)(colBase + row) * KTOT + kc + seg * 8;
            cp16(s0 + OFF_BH + row * ROWB + seg * 16, Bh + go);
            cp16(s0 + OFF_BL + row * ROWB + seg * 16, Bl + go);
        }
        CP_COMMIT();
    };

    float acc[4][4][4];
    #pragma unroll
    for (int mt = 0; mt < 4; ++mt)
        #pragma unroll
        for (int nt = 0; nt < 4; ++nt)
            #pragma unroll
            for (int i = 0; i < 4; ++i) acc[mt][nt][i] = 0.f;

    load_stage(0);

    for (int c = 0; c < NCHUNK; ++c) {
        CP_WAIT0();
        __syncthreads();
        if (c + 1 < NCHUNK) load_stage(c + 1);

        const uint32_t sb = sb0 + (c & 1) * STAGE;

        #pragma unroll
        for (int kk = 0; kk < BK / 16; ++kk) {
            const uint32_t ab = sb + (uint32_t)(a_row * ROWB + kk * 32 + a_kby);
            const uint32_t bb = sb + (uint32_t)(b_row * ROWB + kk * 32 + b_kby);

            uint32_t aF[4][4], bF[2][4];

            // ---- pass 1: HH (16 independent MMAs) ----
            #pragma unroll
            for (int mt = 0; mt < 4; ++mt) ldm_x4(aF[mt], ab + OFF_AH + mt * 16 * ROWB);
            #pragma unroll
            for (int ne = 0; ne < 2; ++ne) ldm_x4(bF[ne], bb + OFF_BH + ne * 16 * ROWB);
            #pragma unroll
            for (int mt = 0; mt < 4; ++mt)
                #pragma unroll
                for (int nt = 0; nt < 4; ++nt) {
                    const int ne = nt >> 1, h2 = (nt & 1) * 2;
                    MMA(acc[mt][nt], aF[mt], bF[ne][h2], bF[ne][h2 + 1]);
                }

            // ---- pass 2: HL (reuse aH, load bL) ----
            uint32_t bL[2][4];
            #pragma unroll
            for (int ne = 0; ne < 2; ++ne) ldm_x4(bL[ne], bb + OFF_BL + ne * 16 * ROWB);
            #pragma unroll
            for (int mt = 0; mt < 4; ++mt)
                #pragma unroll
                for (int nt = 0; nt < 4; ++nt) {
                    const int ne = nt >> 1, h2 = (nt & 1) * 2;
                    MMA(acc[mt][nt], aF[mt], bL[ne][h2], bL[ne][h2 + 1]);
                }

            // ---- pass 3: LH (load aL, reuse bH) ----
            #pragma unroll
            for (int mt = 0; mt < 4; ++mt) ldm_x4(aF[mt], ab + OFF_AL + mt * 16 * ROWB);
            #pragma unroll
            for (int mt = 0; mt < 4; ++mt)
                #pragma unroll
                for (int nt = 0; nt < 4; ++nt) {
                    const int ne = nt >> 1, h2 = (nt & 1) * 2;
                    MMA(acc[mt][nt], aF[mt], bF[ne][h2], bF[ne][h2 + 1]);
                }
        }
        __syncthreads();
    }

    // ---------------- Epilogue ----------------
    if constexpr (EPI == 0 || EPI == 1) {
        __nv_bfloat16* Dh = (EPI == 0) ? g_kh : g_hh;
        __nv_bfloat16* Dl = (EPI == 0) ? g_kl : g_hl;
        #pragma unroll
        for (int mt = 0; mt < 4; ++mt) {
            int r0 = rowBase + warp_m * 64 + mt * 16 + g;
            float x0 = 0.f, x1 = 0.f;
            if (EPI == 0) { x0 = g_x2[r0]; x1 = g_x2[r0 + 8]; }
            #pragma unroll
            for (int nt = 0; nt < 4; ++nt) {
                int cidx = colBase + warp_n * 32 + nt * 8 + 2 * tg;
                float v00, v01, v10, v11;
                if (EPI == 0) {
                    float s0v = g_s2[cidx], s1v = g_s2[cidx + 1];
                    v00 = __expf(GAMMA_F * (2.f * acc[mt][nt][0] - x0 - s0v));
                    v01 = __expf(GAMMA_F * (2.f * acc[mt][nt][1] - x0 - s1v));
                    v10 = __expf(GAMMA_F * (2.f * acc[mt][nt][2] - x1 - s0v));
                    v11 = __expf(GAMMA_F * (2.f * acc[mt][nt][3] - x1 - s1v));
                } else {
                    float b0v = bias[cidx], b1v = bias[cidx + 1];
                    v00 = fmaxf(acc[mt][nt][0] + b0v, 0.f);
                    v01 = fmaxf(acc[mt][nt][1] + b1v, 0.f);
                    v10 = fmaxf(acc[mt][nt][2] + b0v, 0.f);
                    v11 = fmaxf(acc[mt][nt][3] + b1v, 0.f);
                }
                __nv_bfloat162 h, l;
                size_t o0 = (size_t)r0 * S_DIM + cidx;
                size_t o1 = (size_t)(r0 + 8) * S_DIM + cidx;
                split2(v00, v01, h, l);
                *(__nv_bfloat162*)(Dh + o0) = h; *(__nv_bfloat162*)(Dl + o0) = l;
                split2(v10, v11, h, l);
                *(__nv_bfloat162*)(Dh + o1) = h; *(__nv_bfloat162*)(Dl + o1) = l;
            }
        }
    } else {
        float o0s[4][2], o1s[4][2];
        #pragma unroll
        for (int mt = 0; mt < 4; ++mt) { o0s[mt][0] = o0s[mt][1] = 0.f;
                                         o1s[mt][0] = o1s[mt][1] = 0.f; }
        #pragma unroll
        for (int nt = 0; nt < 4; ++nt) {
            int cidx = colBase + warp_n * 32 + nt * 8 + 2 * tg;
            float b0v = bias[cidx], b1v = bias[cidx + 1];
            float w00 = Wh[cidx],         w01 = Wh[cidx + 1];
            float w10 = Wh[S_DIM + cidx], w11 = Wh[S_DIM + cidx + 1];
            #pragma unroll
            for (int mt = 0; mt < 4; ++mt) {
                float v00 = fmaxf(acc[mt][nt][0] + b0v, 0.f);
                float v01 = fmaxf(acc[mt][nt][1] + b1v, 0.f);
                float v10 = fmaxf(acc[mt][nt][2] + b0v, 0.f);
                float v11 = fmaxf(acc[mt][nt][3] + b1v, 0.f);
                o0s[mt][0] = fmaf(v00, w00, fmaf(v01, w01, o0s[mt][0]));
                o1s[mt][0] = fmaf(v00, w10, fmaf(v01, w11, o1s[mt][0]));
                o0s[mt][1] = fmaf(v10, w00, fmaf(v11, w01, o0s[mt][1]));
                o1s[mt][1] = fmaf(v10, w10, fmaf(v11, w11, o1s[mt][1]));
            }
        }
        #pragma unroll
        for (int mt = 0; mt < 4; ++mt)
            #pragma unroll
            for (int rh = 0; rh < 2; ++rh) {
                float a = o0s[mt][rh], b = o1s[mt][rh];
                a += __shfl_xor_sync(0xffffffffu, a, 1);
                a += __shfl_xor_sync(0xffffffffu, a, 2);
                b += __shfl_xor_sync(0xffffffffu, b, 1);
                b += __shfl_xor_sync(0xffffffffu, b, 2);
                o0s[mt][rh] = a; o1s[mt][rh] = b;
            }
        if (tg == 0) {
            int slot = blockIdx.x * 8 + warp_n;   // 0..31
            #pragma unroll
            for (int mt = 0; mt < 4; ++mt)
                #pragma unroll
                for (int rh = 0; rh < 2; ++rh) {
                    int row = rowBase + warp_m * 64 + mt * 16 + g + rh * 8;
                    size_t base = ((size_t)slot * B_ROWS + row) * 2;
                    g_part[base]     = o0s[mt][rh];
                    g_part[base + 1] = o1s[mt][rh];
                }
        }
    }
}

// ============================================================================
// Small kernels
// ============================================================================
// Row-wise split + fused sum-of-squares (one warp per row).  COLS % 128 == 0.
template <int COLS>
__global__ void split_rows(const float* __restrict__ src,
                           __nv_bfloat16* __restrict__ hi,
                           __nv_bfloat16* __restrict__ lo,
                           float* __restrict__ nrm) {
    int row  = blockIdx.x * 8 + (threadIdx.x >> 5);
    int lane = threadIdx.x & 31;
    const float4* s = (const float4*)(src + (size_t)row * COLS);
    __nv_bfloat162* h2 = (__nv_bfloat162*)(hi + (size_t)row * COLS);
    __nv_bfloat162* l2 = (__nv_bfloat162*)(lo + (size_t)row * COLS);
    float ss = 0.f;
    #pragma unroll
    for (int i = 0; i < COLS / 128; ++i) {
        float4 v = s[i * 32 + lane];
        ss = fmaf(v.x, v.x, fmaf(v.y, v.y, fmaf(v.z, v.z, fmaf(v.w, v.w, ss))));
        __nv_bfloat162 ha, la, hb, lb;
        split2(v.x, v.y, ha, la);
        split2(v.z, v.w, hb, lb);
        h2[(i * 32 + lane) * 2]     = ha;
        h2[(i * 32 + lane) * 2 + 1] = hb;
        l2[(i * 32 + lane) * 2]     = la;
        l2[(i * 32 + lane) * 2 + 1] = lb;
    }
    #pragma unroll
    for (int o = 16; o; o >>= 1) ss += __shfl_xor_sync(0xffffffffu, ss, o);
    if (lane == 0) nrm[row] = ss;
}

__global__ void split_kernel(const float* __restrict__ src,
                             __nv_bfloat16* __restrict__ hi,
                             __nv_bfloat16* __restrict__ lo, int n4) {
    int i = blockIdx.x * blockDim.x + threadIdx.x;
    if (i >= n4) return;
    float4 v = ((const float4*)src)[i];
    __nv_bfloat162 h01, l01, h23, l23;
    split2(v.x, v.y, h01, l01);
    split2(v.z, v.w, h23, l23);
    ((__nv_bfloat162*)hi)[2 * i]     = h01;
    ((__nv_bfloat162*)hi)[2 * i + 1] = h23;
    ((__nv_bfloat162*)lo)[2 * i]     = l01;
    ((__nv_bfloat162*)lo)[2 * i + 1] = l23;
}

__global__ void head_final(const float* __restrict__ bh, float* __restrict__ out) {
    int i = blockIdx.x * blockDim.x + threadIdx.x;
    if (i < B_ROWS * 2) {
        float s = bh[i & 1];
        #pragma unroll
        for (int t = 0; t < 32; ++t) s += g_part[(size_t)t * B_ROWS * 2 + i];
        out[i] = s;
    }
}

// ============================================================================
// Launcher — GEMMs placed at launch indices 2 and 5 so ncu captures one.
// ============================================================================
extern "C" void kernel_launch(void* const* d_in, const int* in_sizes, int n_in,
                              void* d_out, int out_size) {
    (void)in_sizes; (void)n_in; (void)out_size;
    const float* x  = (const float*)d_in[0];
    const float* sv = (const float*)d_in[1];
    const float* W1 = (const float*)d_in[2];
    const float* b1 = (const float*)d_in[3];
    const float* W2 = (const float*)d_in[4];
    const float* b2 = (const float*)d_in[5];
    const float* Wh = (const float*)d_in[6];
    const float* bh = (const float*)d_in[7];
    float* out = (float*)d_out;

    static __nv_bfloat16 *xh, *xl, *svh, *svl, *w1h, *w1l, *w2h, *w2l,
                         *kh, *kl, *hh, *hl;
    static float *x2p, *s2p;
    static bool got = false;
    if (!got) {
        cudaGetSymbolAddress((void**)&xh,  g_xh);  cudaGetSymbolAddress((void**)&xl,  g_xl);
        cudaGetSymbolAddress((void**)&svh, g_svh); cudaGetSymbolAddress((void**)&svl, g_svl);
        cudaGetSymbolAddress((void**)&w1h, g_w1h); cudaGetSymbolAddress((void**)&w1l, g_w1l);
        cudaGetSymbolAddress((void**)&w2h, g_w2h); cudaGetSymbolAddress((void**)&w2l, g_w2l);
        cudaGetSymbolAddress((void**)&kh,  g_kh);  cudaGetSymbolAddress((void**)&kl,  g_kl);
        cudaGetSymbolAddress((void**)&hh,  g_hh);  cudaGetSymbolAddress((void**)&hl,  g_hl);
        cudaGetSymbolAddress((void**)&x2p, g_x2);  cudaGetSymbolAddress((void**)&s2p, g_s2);
        cudaFuncSetAttribute((const void*)gemm_hmma<FEAT, 0>,
                             cudaFuncAttributeMaxDynamicSharedMemorySize, SMEM_TOTAL);
        cudaFuncSetAttribute((const void*)gemm_hmma<S_DIM, 1>,
                             cudaFuncAttributeMaxDynamicSharedMemorySize, SMEM_TOTAL);
        cudaFuncSetAttribute((const void*)gemm_hmma<S_DIM, 2>,
                             cudaFuncAttributeMaxDynamicSharedMemorySize, SMEM_TOTAL);
        got = true;
    }

    dim3 grid(S_DIM / BN, B_ROWS / BM);   // (4, 512)

    // idx 0, 1: input splits (+ fused row norms)
    split_rows<FEAT><<<B_ROWS / 8, 256>>>(x,  xh,  xl,  x2p);
    split_rows<FEAT><<<S_DIM  / 8, 256>>>(sv, svh, svl, s2p);
    // idx 2: GEMM1 (needs only x/sv splits)
    gemm_hmma<FEAT, 0><<<grid, NTH, SMEM_TOTAL>>>(xh, xl, svh, svl, nullptr, nullptr);
    // idx 3, 4: weight splits
    split_kernel<<<(S_DIM * S_DIM / 4 + 255) / 256, 256>>>(W1, w1h, w1l, S_DIM * S_DIM / 4);
    split_kernel<<<(S_DIM * S_DIM / 4 + 255) / 256, 256>>>(W2, w2h, w2l, S_DIM * S_DIM / 4);
    // idx 5: GEMM2
    gemm_hmma<S_DIM, 1><<<grid, NTH, SMEM_TOTAL>>>(kh, kl, w1h, w1l, b1, nullptr);
    // idx 6: GEMM3
    gemm_hmma<S_DIM, 2><<<grid, NTH, SMEM_TOTAL>>>(hh, hl, w2h, w2l, b2, Wh);
    // idx 7: head reduction
    head_final<<<(B_ROWS * 2 + 255) / 256, 256>>>(bh, out);
}

// round 7
// speedup vs baseline: 1.6142x; 1.5802x over previous
#include <cuda_runtime.h>
#include <cstdint>

// ============================================================================
// Problem constants
// ============================================================================
#define GAMMA_F 0.00390625f

constexpr int B_ROWS = 65536;
constexpr int FEAT   = 256;
constexpr int S_DIM  = 1024;

// GEMM tiling: CTA 128x128, K-chunk 128 (int8), 8 warps of 64x32
constexpr int BM  = 128;
constexpr int BN  = 128;
constexpr int BK  = 128;
constexpr int NTH = 256;

// SMEM rows padded 128B -> 144B (9x16B: ldmatrix rows hit 8 distinct groups)
constexpr int ROWB    = BK + 16;           // 144 bytes per row
constexpr int A_PLANE = BM * ROWB;         // 18432
constexpr int B_PLANE = BN * ROWB;         // 18432
constexpr int OFF_A1  = 0;
constexpr int OFF_A2  = A_PLANE;
constexpr int OFF_B1  = 2 * A_PLANE;
constexpr int OFF_B2  = 2 * A_PLANE + B_PLANE;
constexpr int STAGE   = 2 * A_PLANE + 2 * B_PLANE;   // 73728
constexpr int SMEM_TOTAL = 2 * STAGE;                // 147456

constexpr float INV254 = 1.0f / 254.0f;
constexpr float INVQ   = 1.0f / 16129.0f;   // 1/127^2

// ============================================================================
// Device scratch (__device__ globals: alloc-free rule)
// ============================================================================
__device__ __align__(16) int8_t g_xa [(size_t)B_ROWS * FEAT];
__device__ __align__(16) int8_t g_xb [(size_t)B_ROWS * FEAT];
__device__ __align__(16) int8_t g_sva[(size_t)S_DIM * FEAT];
__device__ __align__(16) int8_t g_svb[(size_t)S_DIM * FEAT];
__device__ __align__(16) int8_t g_w1a[(size_t)S_DIM * S_DIM];
__device__ __align__(16) int8_t g_w1b[(size_t)S_DIM * S_DIM];
__device__ __align__(16) int8_t g_w2a[(size_t)S_DIM * S_DIM];
__device__ __align__(16) int8_t g_w2b[(size_t)S_DIM * S_DIM];
__device__ __align__(16) int8_t g_ka [(size_t)B_ROWS * S_DIM];
__device__ __align__(16) int8_t g_kb [(size_t)B_ROWS * S_DIM];
__device__ __align__(16) int8_t g_ha [(size_t)B_ROWS * S_DIM];
__device__ __align__(16) int8_t g_hb [(size_t)B_ROWS * S_DIM];
__device__ __align__(16) float  g_hf [(size_t)B_ROWS * S_DIM];   // fp32 hidden1
__device__ float g_xs [B_ROWS];   // quant scales
__device__ float g_svs[S_DIM];
__device__ float g_w1s[S_DIM];
__device__ float g_w2s[S_DIM];
__device__ float g_hs [B_ROWS];
__device__ float g_xn [B_ROWS];   // squared norms
__device__ float g_svn[S_DIM];
__device__ float g_part[32 * B_ROWS * 2];

// ============================================================================
// PTX helpers (sm_100 baseline: cp.async + ldmatrix + mma.sync s8)
// ============================================================================
__device__ __forceinline__ uint32_t smem_u32(const void* p) {
    uint32_t a;
    asm("{ .reg .u64 t; cvta.to.shared.u64 t, %1; cvt.u32.u64 %0, t; }"
        : "=r"(a) : "l"(p));
    return a;
}

__device__ __forceinline__ void cp16(uint32_t s, const void* g) {
    asm volatile("cp.async.cg.shared.global [%0], [%1], 16;"
                 :: "r"(s), "l"((unsigned long long)(uintptr_t)g) : "memory");
}
#define CP_COMMIT()  asm volatile("cp.async.commit_group;" ::: "memory")
#define CP_WAIT0()   asm volatile("cp.async.wait_group 0;" ::: "memory")

__device__ __forceinline__ void ldm_x4(uint32_t* r, uint32_t saddr) {
    asm volatile("ldmatrix.sync.aligned.m8n8.x4.shared.b16 {%0,%1,%2,%3}, [%4];"
                 : "=r"(r[0]), "=r"(r[1]), "=r"(r[2]), "=r"(r[3]) : "r"(saddr));
}

// mma.sync m16n8k32 s8 x s8 -> s32
#define IMMA(C, A, B0, B1)                                                     \
    asm volatile(                                                              \
        "mma.sync.aligned.m16n8k32.row.col.s32.s8.s8.s32 "                     \
        "{%0,%1,%2,%3}, {%4,%5,%6,%7}, {%8,%9}, {%0,%1,%2,%3};"                \
        : "+r"((C)[0]), "+r"((C)[1]), "+r"((C)[2]), "+r"((C)[3])               \
        : "r"((A)[0]), "r"((A)[1]), "r"((A)[2]), "r"((A)[3]),                  \
          "r"(B0), "r"(B1))

// fp32 -> 2-slice int8 (scale s baked into inv = 127/s)
__device__ __forceinline__ void qpair(float v, float inv, int8_t& o1, int8_t& o2) {
    float q = v * inv;
    float R = rintf(q);
    o1 = (int8_t)(int)R;
    o2 = (int8_t)(int)rintf((q - R) * 254.0f);
}

// ============================================================================
// Row-wise 2-slice quantizer (warp per row). Optionally emits sum-of-squares.
// ============================================================================
template <int COLS, bool NORM>
__global__ void quant_rows(const float* __restrict__ src,
                           int8_t* __restrict__ q1, int8_t* __restrict__ q2,
                           float* __restrict__ sOut, float* __restrict__ nrm) {
    int row  = blockIdx.x * 8 + (threadIdx.x >> 5);
    int lane = threadIdx.x & 31;
    const float4* s4 = (const float4*)(src + (size_t)row * COLS);
    float4 vb[COLS / 128];
    float mx = 0.f, ss = 0.f;
    #pragma unroll
    for (int i = 0; i < COLS / 128; ++i) {
        float4 v = s4[i * 32 + lane];
        vb[i] = v;
        mx = fmaxf(mx, fmaxf(fmaxf(fabsf(v.x), fabsf(v.y)),
                             fmaxf(fabsf(v.z), fabsf(v.w))));
        if (NORM)
            ss = fmaf(v.x, v.x, fmaf(v.y, v.y, fmaf(v.z, v.z, fmaf(v.w, v.w, ss))));
    }
    #pragma unroll
    for (int o = 16; o; o >>= 1) {
        mx = fmaxf(mx, __shfl_xor_sync(0xffffffffu, mx, o));
        if (NORM) ss += __shfl_xor_sync(0xffffffffu, ss, o);
    }
    float s = mx > 0.f ? mx : 1.0f;
    if (lane == 0) {
        sOut[row] = s;
        if (NORM) nrm[row] = ss;
    }
    float inv = 127.0f / s;
    #pragma unroll
    for (int i = 0; i < COLS / 128; ++i) {
        char4 c1, c2;
        qpair(vb[i].x, inv, (int8_t&)c1.x, (int8_t&)c2.x);
        qpair(vb[i].y, inv, (int8_t&)c1.y, (int8_t&)c2.y);
        qpair(vb[i].z, inv, (int8_t&)c1.z, (int8_t&)c2.z);
        qpair(vb[i].w, inv, (int8_t&)c1.w, (int8_t&)c2.w);
        size_t o = (size_t)row * COLS + i * 128 + lane * 4;
        *(char4*)(q1 + o) = c1;
        *(char4*)(q2 + o) = c2;
    }
}

// ============================================================================
// Int8 2-slice GEMM.  D[m,n] = sum_k A[m,k] * B[n,k]
//  dot = (C1 + Cx/254) * sA*sB/127^2,  C1 = A1B1, Cx = A1B2 + A2B1
//  EPI 0: k = exp(g*(2*dot - xn - svn)) -> g_ka/g_kb (scale 1)
//  EPI 1: h = relu(dot + b1)            -> g_hf (fp32)
//  EPI 2: v = relu(dot + b2); head partials -> g_part
// ============================================================================
template <int KTOT, int EPI>
__global__ void __launch_bounds__(NTH, 1)
gemm_i8(const int8_t* __restrict__ A1p, const int8_t* __restrict__ A2p,
        const int8_t* __restrict__ B1p, const int8_t* __restrict__ B2p,
        const float* __restrict__ sA, const float* __restrict__ sB,
        const float* __restrict__ bias, const float* __restrict__ Wh) {
    extern __shared__ char smem[];
    const uint32_t sb0 = smem_u32(smem);

    const int tid    = threadIdx.x;
    const int wid    = tid >> 5;
    const int lane   = tid & 31;
    const int g      = lane >> 2;
    const int tg     = lane & 3;
    const int warp_m = wid & 1;         // 0..1  (64-row halves)
    const int warp_n = wid >> 1;        // 0..3  (32-col slices)

    const int rowBase = blockIdx.y * BM;
    const int colBase = blockIdx.x * BN;
    constexpr int NCHUNK = KTOT / BK;

    // ldmatrix lane-address components (byte units; k32 frag = b16 k16 layout)
    const int a_row = warp_m * 64 + (lane & 7) + ((lane >> 3) & 1) * 8;
    const int a_kby = (lane >> 4) * 16;
    const int b_row = warp_n * 32 + (lane & 7) + (lane >> 4) * 8;
    const int b_kby = ((lane >> 3) & 1) * 16;

    auto load_stage = [&](int c) {
        uint32_t s0 = sb0 + (c & 1) * STAGE;
        const int kc = c * BK;
        #pragma unroll
        for (int u = tid; u < BM * 8; u += NTH) {
            int row = u >> 3, seg = u & 7;
            size_t go = (size_t)(rowBase + row) * KTOT + kc + seg * 16;
            cp16(s0 + OFF_A1 + row * ROWB + seg * 16, A1p + go);
            cp16(s0 + OFF_A2 + row * ROWB + seg * 16, A2p + go);
        }
        #pragma unroll
        for (int u = tid; u < BN * 8; u += NTH) {
            int row = u >> 3, seg = u & 7;
            size_t go = (size_t)(colBase + row) * KTOT + kc + seg * 16;
            cp16(s0 + OFF_B1 + row * ROWB + seg * 16, B1p + go);
            cp16(s0 + OFF_B2 + row * ROWB + seg * 16, B2p + go);
        }
        CP_COMMIT();
    };

    int C1[4][4][4], Cx[4][4][4];
    #pragma unroll
    for (int mt = 0; mt < 4; ++mt)
        #pragma unroll
        for (int nt = 0; nt < 4; ++nt)
            #pragma unroll
            for (int i = 0; i < 4; ++i) { C1[mt][nt][i] = 0; Cx[mt][nt][i] = 0; }

    load_stage(0);

    for (int c = 0; c < NCHUNK; ++c) {
        CP_WAIT0();
        __syncthreads();
        if (c + 1 < NCHUNK) load_stage(c + 1);

        const uint32_t sb = sb0 + (c & 1) * STAGE;

        #pragma unroll
        for (int kk = 0; kk < BK / 32; ++kk) {
            const uint32_t ab = sb + (uint32_t)(a_row * ROWB + kk * 32 + a_kby);
            const uint32_t bb = sb + (uint32_t)(b_row * ROWB + kk * 32 + b_kby);

            uint32_t aF[4][4], bF[2][4], bG[2][4];

            // pass 1: A1*B1 -> C1
            #pragma unroll
            for (int mt = 0; mt < 4; ++mt) ldm_x4(aF[mt], ab + OFF_A1 + mt * 16 * ROWB);
            #pragma unroll
            for (int ne = 0; ne < 2; ++ne) ldm_x4(bF[ne], bb + OFF_B1 + ne * 16 * ROWB);
            #pragma unroll
            for (int mt = 0; mt < 4; ++mt)
                #pragma unroll
                for (int nt = 0; nt < 4; ++nt) {
                    const int ne = nt >> 1, h2 = (nt & 1) * 2;
                    IMMA(C1[mt][nt], aF[mt], bF[ne][h2], bF[ne][h2 + 1]);
                }

            // pass 2: A1*B2 -> Cx
            #pragma unroll
            for (int ne = 0; ne < 2; ++ne) ldm_x4(bG[ne], bb + OFF_B2 + ne * 16 * ROWB);
            #pragma unroll
            for (int mt = 0; mt < 4; ++mt)
                #pragma unroll
                for (int nt = 0; nt < 4; ++nt) {
                    const int ne = nt >> 1, h2 = (nt & 1) * 2;
                    IMMA(Cx[mt][nt], aF[mt], bG[ne][h2], bG[ne][h2 + 1]);
                }

            // pass 3: A2*B1 -> Cx
            #pragma unroll
            for (int mt = 0; mt < 4; ++mt) ldm_x4(aF[mt], ab + OFF_A2 + mt * 16 * ROWB);
            #pragma unroll
            for (int mt = 0; mt < 4; ++mt)
                #pragma unroll
                for (int nt = 0; nt < 4; ++nt) {
                    const int ne = nt >> 1, h2 = (nt & 1) * 2;
                    IMMA(Cx[mt][nt], aF[mt], bF[ne][h2], bF[ne][h2 + 1]);
                }
        }
        __syncthreads();
    }

    // ---------------- Epilogue ----------------
    float o0s[4][2], o1s[4][2];
    if constexpr (EPI == 2) {
        #pragma unroll
        for (int mt = 0; mt < 4; ++mt) { o0s[mt][0] = o0s[mt][1] = 0.f;
                                         o1s[mt][0] = o1s[mt][1] = 0.f; }
    }

    #pragma unroll
    for (int mt = 0; mt < 4; ++mt) {
        const int r0 = rowBase + warp_m * 64 + mt * 16 + g;
        const float sa0 = sA ? sA[r0] : 1.0f;
        const float sa1 = sA ? sA[r0 + 8] : 1.0f;
        float xn0 = 0.f, xn1 = 0.f;
        if (EPI == 0) { xn0 = g_xn[r0]; xn1 = g_xn[r0 + 8]; }

        #pragma unroll
        for (int nt = 0; nt < 4; ++nt) {
            const int cidx = colBase + warp_n * 32 + nt * 8 + 2 * tg;
            const float q0 = sB[cidx] * INVQ, q1 = sB[cidx + 1] * INVQ;
            float d00 = ((float)C1[mt][nt][0] + (float)Cx[mt][nt][0] * INV254) * (sa0 * q0);
            float d01 = ((float)C1[mt][nt][1] + (float)Cx[mt][nt][1] * INV254) * (sa0 * q1);
            float d10 = ((float)C1[mt][nt][2] + (float)Cx[mt][nt][2] * INV254) * (sa1 * q0);
            float d11 = ((float)C1[mt][nt][3] + (float)Cx[mt][nt][3] * INV254) * (sa1 * q1);

            if constexpr (EPI == 0) {
                float sn0 = g_svn[cidx], sn1 = g_svn[cidx + 1];
                float k00 = __expf(GAMMA_F * (2.f * d00 - xn0 - sn0));
                float k01 = __expf(GAMMA_F * (2.f * d01 - xn0 - sn1));
                float k10 = __expf(GAMMA_F * (2.f * d10 - xn1 - sn0));
                float k11 = __expf(GAMMA_F * (2.f * d11 - xn1 - sn1));
                char2 p1, p2;
                size_t o0 = (size_t)r0 * S_DIM + cidx;
                size_t o1 = (size_t)(r0 + 8) * S_DIM + cidx;
                qpair(k00, 127.0f, (int8_t&)p1.x, (int8_t&)p2.x);
                qpair(k01, 127.0f, (int8_t&)p1.y, (int8_t&)p2.y);
                *(char2*)(g_ka + o0) = p1; *(char2*)(g_kb + o0) = p2;
                qpair(k10, 127.0f, (int8_t&)p1.x, (int8_t&)p2.x);
                qpair(k11, 127.0f, (int8_t&)p1.y, (int8_t&)p2.y);
                *(char2*)(g_ka + o1) = p1; *(char2*)(g_kb + o1) = p2;
            } else if constexpr (EPI == 1) {
                float b0v = bias[cidx], b1v = bias[cidx + 1];
                float2 h0 = make_float2(fmaxf(d00 + b0v, 0.f), fmaxf(d01 + b1v, 0.f));
                float2 h1 = make_float2(fmaxf(d10 + b0v, 0.f), fmaxf(d11 + b1v, 0.f));
                *(float2*)(g_hf + (size_t)r0 * S_DIM + cidx)       = h0;
                *(float2*)(g_hf + (size_t)(r0 + 8) * S_DIM + cidx) = h1;
            } else {
                float b0v = bias[cidx], b1v = bias[cidx + 1];
                float w00 = Wh[cidx],         w01 = Wh[cidx + 1];
                float w10 = Wh[S_DIM + cidx], w11 = Wh[S_DIM + cidx + 1];
                float v00 = fmaxf(d00 + b0v, 0.f), v01 = fmaxf(d01 + b1v, 0.f);
                float v10 = fmaxf(d10 + b0v, 0.f), v11 = fmaxf(d11 + b1v, 0.f);
                o0s[mt][0] = fmaf(v00, w00, fmaf(v01, w01, o0s[mt][0]));
                o1s[mt][0] = fmaf(v00, w10, fmaf(v01, w11, o1s[mt][0]));
                o0s[mt][1] = fmaf(v10, w00, fmaf(v11, w01, o0s[mt][1]));
                o1s[mt][1] = fmaf(v10, w10, fmaf(v11, w11, o1s[mt][1]));
            }
        }
    }

    if constexpr (EPI == 2) {
        #pragma unroll
        for (int mt = 0; mt < 4; ++mt)
            #pragma unroll
            for (int rh = 0; rh < 2; ++rh) {
                float a = o0s[mt][rh], b = o1s[mt][rh];
                a += __shfl_xor_sync(0xffffffffu, a, 1);
                a += __shfl_xor_sync(0xffffffffu, a, 2);
                b += __shfl_xor_sync(0xffffffffu, b, 1);
                b += __shfl_xor_sync(0xffffffffu, b, 2);
                o0s[mt][rh] = a; o1s[mt][rh] = b;
            }
        if (tg == 0) {
            int slot = blockIdx.x * 4 + warp_n;   // 0..31
            #pragma unroll
            for (int mt = 0; mt < 4; ++mt)
                #pragma unroll
                for (int rh = 0; rh < 2; ++rh) {
                    int row = rowBase + warp_m * 64 + mt * 16 + g + rh * 8;
                    size_t base = ((size_t)slot * B_ROWS + row) * 2;
                    g_part[base]     = o0s[mt][rh];
                    g_part[base + 1] = o1s[mt][rh];
                }
        }
    }
}

// ============================================================================
// Head reduction
// ============================================================================
__global__ void head_final(const float* __restrict__ bh, float* __restrict__ out) {
    int i = blockIdx.x * blockDim.x + threadIdx.x;
    if (i < B_ROWS * 2) {
        float s = bh[i & 1];
        #pragma unroll
        for (int t = 0; t < 32; ++t) s += g_part[(size_t)t * B_ROWS * 2 + i];
        out[i] = s;
    }
}

// ============================================================================
// Launcher — GEMMs at launch indices 3 and 4 (ncu capture window)
// ============================================================================
extern "C" void kernel_launch(void* const* d_in, const int* in_sizes, int n_in,
                              void* d_out, int out_size) {
    (void)in_sizes; (void)n_in; (void)out_size;
    const float* x  = (const float*)d_in[0];
    const float* sv = (const float*)d_in[1];
    const float* W1 = (const float*)d_in[2];
    const float* b1 = (const float*)d_in[3];
    const float* W2 = (const float*)d_in[4];
    const float* b2 = (const float*)d_in[5];
    const float* Wh = (const float*)d_in[6];
    const float* bh = (const float*)d_in[7];
    float* out = (float*)d_out;

    static int8_t *xa, *xb, *sva, *svb, *w1a, *w1b, *w2a, *w2b, *ka, *kb, *ha, *hb;
    static float *hf, *xs, *svs, *w1s, *w2s, *hs, *xn, *svn;
    static bool got = false;
    if (!got) {
        cudaGetSymbolAddress((void**)&xa,  g_xa);  cudaGetSymbolAddress((void**)&xb,  g_xb);
        cudaGetSymbolAddress((void**)&sva, g_sva); cudaGetSymbolAddress((void**)&svb, g_svb);
        cudaGetSymbolAddress((void**)&w1a, g_w1a); cudaGetSymbolAddress((void**)&w1b, g_w1b);
        cudaGetSymbolAddress((void**)&w2a, g_w2a); cudaGetSymbolAddress((void**)&w2b, g_w2b);
        cudaGetSymbolAddress((void**)&ka,  g_ka);  cudaGetSymbolAddress((void**)&kb,  g_kb);
        cudaGetSymbolAddress((void**)&ha,  g_ha);  cudaGetSymbolAddress((void**)&hb,  g_hb);
        cudaGetSymbolAddress((void**)&hf,  g_hf);
        cudaGetSymbolAddress((void**)&xs,  g_xs);  cudaGetSymbolAddress((void**)&svs, g_svs);
        cudaGetSymbolAddress((void**)&w1s, g_w1s); cudaGetSymbolAddress((void**)&w2s, g_w2s);
        cudaGetSymbolAddress((void**)&hs,  g_hs);
        cudaGetSymbolAddress((void**)&xn,  g_xn);  cudaGetSymbolAddress((void**)&svn, g_svn);
        cudaFuncSetAttribute((const void*)gemm_i8<FEAT, 0>,
                             cudaFuncAttributeMaxDynamicSharedMemorySize, SMEM_TOTAL);
        cudaFuncSetAttribute((const void*)gemm_i8<S_DIM, 1>,
                             cudaFuncAttributeMaxDynamicSharedMemorySize, SMEM_TOTAL);
        cudaFuncSetAttribute((const void*)gemm_i8<S_DIM, 2>,
                             cudaFuncAttributeMaxDynamicSharedMemorySize, SMEM_TOTAL);
        got = true;
    }

    dim3 grid(S_DIM / BN, B_ROWS / BM);   // (8, 512)

    // idx 0-2: quantize x (+norm), sv (+norm), W1
    quant_rows<FEAT, true ><<<B_ROWS / 8, 256>>>(x,  xa,  xb,  xs,  xn);
    quant_rows<FEAT, true ><<<S_DIM  / 8, 256>>>(sv, sva, svb, svs, svn);
    quant_rows<S_DIM, false><<<S_DIM / 8, 256>>>(W1, w1a, w1b, w1s, nullptr);
    // idx 3: GEMM1 (RBF features, writes int8 k directly, scale 1)
    gemm_i8<FEAT, 0><<<grid, NTH, SMEM_TOTAL>>>(xa, xb, sva, svb, xs, svs, nullptr, nullptr);
    // idx 4: GEMM2 (hidden1, fp32 out)
    gemm_i8<S_DIM, 1><<<grid, NTH, SMEM_TOTAL>>>(ka, kb, w1a, w1b, nullptr, w1s, b1, nullptr);
    // idx 5-6: quantize W2, requantize h (row max)
    quant_rows<S_DIM, false><<<S_DIM / 8, 256>>>(W2, w2a, w2b, w2s, nullptr);
    quant_rows<S_DIM, false><<<B_ROWS / 8, 256>>>(hf, ha, hb, hs, nullptr);
    // idx 7: GEMM3 (hidden2 + head partials)
    gemm_i8<S_DIM, 2><<<grid, NTH, SMEM_TOTAL>>>(ha, hb, w2a, w2b, hs, w2s, b2, Wh);
    // idx 8: head reduction
    head_final<<<(B_ROWS * 2 + 255) / 256, 256>>>(bh, out);
}

// round 8
// speedup vs baseline: 1.7698x; 1.0964x over previous
#include <cuda_runtime.h>
#include <cstdint>

// ============================================================================
// Problem constants
// ============================================================================
#define GAMMA_F 0.00390625f

constexpr int B_ROWS = 65536;
constexpr int FEAT   = 256;
constexpr int S_DIM  = 1024;

// GEMM tiling: CTA 64x128, K-chunk 128 (int8), 8 warps of 32x32, 2 CTAs/SM
constexpr int BM  = 64;
constexpr int BN  = 128;
constexpr int BK  = 128;
constexpr int NTH = 256;

// SMEM rows padded 128B -> 144B (9x16B: ldmatrix rows hit 8 distinct groups)
constexpr int ROWB    = BK + 16;           // 144 bytes per row
constexpr int A_PLANE = BM * ROWB;         // 9216
constexpr int B_PLANE = BN * ROWB;         // 18432
constexpr int OFF_A1  = 0;
constexpr int OFF_A2  = A_PLANE;
constexpr int OFF_B1  = 2 * A_PLANE;
constexpr int OFF_B2  = 2 * A_PLANE + B_PLANE;
constexpr int STAGE   = 2 * A_PLANE + 2 * B_PLANE;   // 55296
constexpr int SMEM_TOTAL = 2 * STAGE;                // 110592 (2 CTAs -> 216K/SM)

constexpr float INV254 = 1.0f / 254.0f;
constexpr float INVQ   = 1.0f / 16129.0f;   // 1/127^2

// ============================================================================
// Device scratch (__device__ globals: alloc-free rule)
// ============================================================================
__device__ __align__(16) int8_t g_xa [(size_t)B_ROWS * FEAT];
__device__ __align__(16) int8_t g_xb [(size_t)B_ROWS * FEAT];
__device__ __align__(16) int8_t g_sva[(size_t)S_DIM * FEAT];
__device__ __align__(16) int8_t g_svb[(size_t)S_DIM * FEAT];
__device__ __align__(16) int8_t g_w1a[(size_t)S_DIM * S_DIM];
__device__ __align__(16) int8_t g_w1b[(size_t)S_DIM * S_DIM];
__device__ __align__(16) int8_t g_w2a[(size_t)S_DIM * S_DIM];
__device__ __align__(16) int8_t g_w2b[(size_t)S_DIM * S_DIM];
__device__ __align__(16) int8_t g_ka [(size_t)B_ROWS * S_DIM];
__device__ __align__(16) int8_t g_kb [(size_t)B_ROWS * S_DIM];
__device__ __align__(16) int8_t g_ha [(size_t)B_ROWS * S_DIM];
__device__ __align__(16) int8_t g_hb [(size_t)B_ROWS * S_DIM];
__device__ __align__(16) float  g_hf [(size_t)B_ROWS * S_DIM];   // fp32 hidden1
__device__ float g_xs [B_ROWS];   // quant scales
__device__ float g_svs[S_DIM];
__device__ float g_w1s[S_DIM];
__device__ float g_w2s[S_DIM];
__device__ float g_hs [B_ROWS];
__device__ float g_xn [B_ROWS];   // squared norms
__device__ float g_svn[S_DIM];
__device__ float g_part[32 * B_ROWS * 2];

// ============================================================================
// PTX helpers (sm_100 baseline: cp.async + ldmatrix + mma.sync s8)
// ============================================================================
__device__ __forceinline__ uint32_t smem_u32(const void* p) {
    uint32_t a;
    asm("{ .reg .u64 t; cvta.to.shared.u64 t, %1; cvt.u32.u64 %0, t; }"
        : "=r"(a) : "l"(p));
    return a;
}

__device__ __forceinline__ void cp16(uint32_t s, const void* g) {
    asm volatile("cp.async.cg.shared.global [%0], [%1], 16;"
                 :: "r"(s), "l"((unsigned long long)(uintptr_t)g) : "memory");
}
#define CP_COMMIT()  asm volatile("cp.async.commit_group;" ::: "memory")
#define CP_WAIT0()   asm volatile("cp.async.wait_group 0;" ::: "memory")

__device__ __forceinline__ void ldm_x4(uint32_t* r, uint32_t saddr) {
    asm volatile("ldmatrix.sync.aligned.m8n8.x4.shared.b16 {%0,%1,%2,%3}, [%4];"
                 : "=r"(r[0]), "=r"(r[1]), "=r"(r[2]), "=r"(r[3]) : "r"(saddr));
}

// mma.sync m16n8k32 s8 x s8 -> s32
#define IMMA(C, A, B0, B1)                                                     \
    asm volatile(                                                              \
        "mma.sync.aligned.m16n8k32.row.col.s32.s8.s8.s32 "                     \
        "{%0,%1,%2,%3}, {%4,%5,%6,%7}, {%8,%9}, {%0,%1,%2,%3};"                \
        : "+r"((C)[0]), "+r"((C)[1]), "+r"((C)[2]), "+r"((C)[3])               \
        : "r"((A)[0]), "r"((A)[1]), "r"((A)[2]), "r"((A)[3]),                  \
          "r"(B0), "r"(B1))

// fp32 -> 2-slice int8 (scale s baked into inv = 127/s)
__device__ __forceinline__ void qpair(float v, float inv, int8_t& o1, int8_t& o2) {
    float q = v * inv;
    float R = rintf(q);
    o1 = (int8_t)(int)R;
    o2 = (int8_t)(int)rintf((q - R) * 254.0f);
}

// ============================================================================
// Row-wise 2-slice quantizer (warp per row). Optionally emits sum-of-squares.
// ============================================================================
template <int COLS, bool NORM>
__global__ void quant_rows(const float* __restrict__ src,
                           int8_t* __restrict__ q1, int8_t* __restrict__ q2,
                           float* __restrict__ sOut, float* __restrict__ nrm) {
    int row  = blockIdx.x * 8 + (threadIdx.x >> 5);
    int lane = threadIdx.x & 31;
    const float4* s4 = (const float4*)(src + (size_t)row * COLS);
    float4 vb[COLS / 128];
    float mx = 0.f, ss = 0.f;
    #pragma unroll
    for (int i = 0; i < COLS / 128; ++i) {
        float4 v = s4[i * 32 + lane];
        vb[i] = v;
        mx = fmaxf(mx, fmaxf(fmaxf(fabsf(v.x), fabsf(v.y)),
                             fmaxf(fabsf(v.z), fabsf(v.w))));
        if (NORM)
            ss = fmaf(v.x, v.x, fmaf(v.y, v.y, fmaf(v.z, v.z, fmaf(v.w, v.w, ss))));
    }
    #pragma unroll
    for (int o = 16; o; o >>= 1) {
        mx = fmaxf(mx, __shfl_xor_sync(0xffffffffu, mx, o));
        if (NORM) ss += __shfl_xor_sync(0xffffffffu, ss, o);
    }
    float s = mx > 0.f ? mx : 1.0f;
    if (lane == 0) {
        sOut[row] = s;
        if (NORM) nrm[row] = ss;
    }
    float inv = 127.0f / s;
    #pragma unroll
    for (int i = 0; i < COLS / 128; ++i) {
        char4 c1, c2;
        qpair(vb[i].x, inv, (int8_t&)c1.x, (int8_t&)c2.x);
        qpair(vb[i].y, inv, (int8_t&)c1.y, (int8_t&)c2.y);
        qpair(vb[i].z, inv, (int8_t&)c1.z, (int8_t&)c2.z);
        qpair(vb[i].w, inv, (int8_t&)c1.w, (int8_t&)c2.w);
        size_t o = (size_t)row * COLS + i * 128 + lane * 4;
        *(char4*)(q1 + o) = c1;
        *(char4*)(q2 + o) = c2;
    }
}

// ============================================================================
// Int8 2-slice GEMM.  D[m,n] = sum_k A[m,k] * B[n,k]
//  dot = (C1 + Cx/254) * sA*sB/127^2,  C1 = A1B1, Cx = A1B2 + A2B1
//  EPI 0: k = exp(g*(2*dot - xn - svn)) -> g_ka/g_kb (scale 1)
//  EPI 1: h = relu(dot + b1)            -> g_hf (fp32)
//  EPI 2: v = relu(dot + b2); head partials -> g_part
// ============================================================================
template <int KTOT, int EPI>
__global__ void __launch_bounds__(NTH, 2)
gemm_i8(const int8_t* __restrict__ A1p, const int8_t* __restrict__ A2p,
        const int8_t* __restrict__ B1p, const int8_t* __restrict__ B2p,
        const float* __restrict__ sA, const float* __restrict__ sB,
        const float* __restrict__ bias, const float* __restrict__ Wh) {
    extern __shared__ char smem[];
    const uint32_t sb0 = smem_u32(smem);

    const int tid    = threadIdx.x;
    const int wid    = tid >> 5;
    const int lane   = tid & 31;
    const int g      = lane >> 2;
    const int tg     = lane & 3;
    const int warp_m = wid & 1;         // 0..1  (32-row halves)
    const int warp_n = wid >> 1;        // 0..3  (32-col slices)

    const int rowBase = blockIdx.y * BM;
    const int colBase = blockIdx.x * BN;
    constexpr int NCHUNK = KTOT / BK;

    // ldmatrix lane-address components (byte units)
    const int a_row = warp_m * 32 + (lane & 7) + ((lane >> 3) & 1) * 8;
    const int a_kby = (lane >> 4) * 16;
    const int b_row = warp_n * 32 + (lane & 7) + (lane >> 4) * 8;
    const int b_kby = ((lane >> 3) & 1) * 16;

    auto load_stage = [&](int c) {
        uint32_t s0 = sb0 + (c & 1) * STAGE;
        const int kc = c * BK;
        #pragma unroll
        for (int u = tid; u < BM * 8; u += NTH) {
            int row = u >> 3, seg = u & 7;
            size_t go = (size_t)(rowBase + row) * KTOT + kc + seg * 16;
            cp16(s0 + OFF_A1 + row * ROWB + seg * 16, A1p + go);
            cp16(s0 + OFF_A2 + row * ROWB + seg * 16, A2p + go);
        }
        #pragma unroll
        for (int u = tid; u < BN * 8; u += NTH) {
            int row = u >> 3, seg = u & 7;
            size_t go = (size_t)(colBase + row) * KTOT + kc + seg * 16;
            cp16(s0 + OFF_B1 + row * ROWB + seg * 16, B1p + go);
            cp16(s0 + OFF_B2 + row * ROWB + seg * 16, B2p + go);
        }
        CP_COMMIT();
    };

    int C1[2][4][4], Cx[2][4][4];
    #pragma unroll
    for (int mt = 0; mt < 2; ++mt)
        #pragma unroll
        for (int nt = 0; nt < 4; ++nt)
            #pragma unroll
            for (int i = 0; i < 4; ++i) { C1[mt][nt][i] = 0; Cx[mt][nt][i] = 0; }

    load_stage(0);

    for (int c = 0; c < NCHUNK; ++c) {
        CP_WAIT0();
        __syncthreads();
        if (c + 1 < NCHUNK) load_stage(c + 1);

        const uint32_t sb = sb0 + (c & 1) * STAGE;

        #pragma unroll
        for (int kk = 0; kk < BK / 32; ++kk) {
            const uint32_t ab = sb + (uint32_t)(a_row * ROWB + kk * 32 + a_kby);
            const uint32_t bb = sb + (uint32_t)(b_row * ROWB + kk * 32 + b_kby);

            uint32_t aF[2][4], bF[2][4], bG[2][4];

            // pass 1: A1*B1 -> C1
            #pragma unroll
            for (int mt = 0; mt < 2; ++mt) ldm_x4(aF[mt], ab + OFF_A1 + mt * 16 * ROWB);
            #pragma unroll
            for (int ne = 0; ne < 2; ++ne) ldm_x4(bF[ne], bb + OFF_B1 + ne * 16 * ROWB);
            #pragma unroll
            for (int mt = 0; mt < 2; ++mt)
                #pragma unroll
                for (int nt = 0; nt < 4; ++nt) {
                    const int ne = nt >> 1, h2 = (nt & 1) * 2;
                    IMMA(C1[mt][nt], aF[mt], bF[ne][h2], bF[ne][h2 + 1]);
                }

            // pass 2: A1*B2 -> Cx
            #pragma unroll
            for (int ne = 0; ne < 2; ++ne) ldm_x4(bG[ne], bb + OFF_B2 + ne * 16 * ROWB);
            #pragma unroll
            for (int mt = 0; mt < 2; ++mt)
                #pragma unroll
                for (int nt = 0; nt < 4; ++nt) {
                    const int ne = nt >> 1, h2 = (nt & 1) * 2;
                    IMMA(Cx[mt][nt], aF[mt], bG[ne][h2], bG[ne][h2 + 1]);
                }

            // pass 3: A2*B1 -> Cx
            #pragma unroll
            for (int mt = 0; mt < 2; ++mt) ldm_x4(aF[mt], ab + OFF_A2 + mt * 16 * ROWB);
            #pragma unroll
            for (int mt = 0; mt < 2; ++mt)
                #pragma unroll
                for (int nt = 0; nt < 4; ++nt) {
                    const int ne = nt >> 1, h2 = (nt & 1) * 2;
                    IMMA(Cx[mt][nt], aF[mt], bF[ne][h2], bF[ne][h2 + 1]);
                }
        }
        __syncthreads();
    }

    // ---------------- Epilogue ----------------
    float o0s[2][2], o1s[2][2];
    if constexpr (EPI == 2) {
        #pragma unroll
        for (int mt = 0; mt < 2; ++mt) { o0s[mt][0] = o0s[mt][1] = 0.f;
                                         o1s[mt][0] = o1s[mt][1] = 0.f; }
    }

    #pragma unroll
    for (int mt = 0; mt < 2; ++mt) {
        const int r0 = rowBase + warp_m * 32 + mt * 16 + g;
        const float sa0 = sA ? sA[r0] : 1.0f;
        const float sa1 = sA ? sA[r0 + 8] : 1.0f;
        float xn0 = 0.f, xn1 = 0.f;
        if (EPI == 0) { xn0 = g_xn[r0]; xn1 = g_xn[r0 + 8]; }

        #pragma unroll
        for (int nt = 0; nt < 4; ++nt) {
            const int cidx = colBase + warp_n * 32 + nt * 8 + 2 * tg;
            const float q0 = sB[cidx] * INVQ, q1 = sB[cidx + 1] * INVQ;
            float d00 = ((float)C1[mt][nt][0] + (float)Cx[mt][nt][0] * INV254) * (sa0 * q0);
            float d01 = ((float)C1[mt][nt][1] + (float)Cx[mt][nt][1] * INV254) * (sa0 * q1);
            float d10 = ((float)C1[mt][nt][2] + (float)Cx[mt][nt][2] * INV254) * (sa1 * q0);
            float d11 = ((float)C1[mt][nt][3] + (float)Cx[mt][nt][3] * INV254) * (sa1 * q1);

            if constexpr (EPI == 0) {
                float sn0 = g_svn[cidx], sn1 = g_svn[cidx + 1];
                float k00 = __expf(GAMMA_F * (2.f * d00 - xn0 - sn0));
                float k01 = __expf(GAMMA_F * (2.f * d01 - xn0 - sn1));
                float k10 = __expf(GAMMA_F * (2.f * d10 - xn1 - sn0));
                float k11 = __expf(GAMMA_F * (2.f * d11 - xn1 - sn1));
                char2 p1, p2;
                size_t o0 = (size_t)r0 * S_DIM + cidx;
                size_t o1 = (size_t)(r0 + 8) * S_DIM + cidx;
                qpair(k00, 127.0f, (int8_t&)p1.x, (int8_t&)p2.x);
                qpair(k01, 127.0f, (int8_t&)p1.y, (int8_t&)p2.y);
                *(char2*)(g_ka + o0) = p1; *(char2*)(g_kb + o0) = p2;
                qpair(k10, 127.0f, (int8_t&)p1.x, (int8_t&)p2.x);
                qpair(k11, 127.0f, (int8_t&)p1.y, (int8_t&)p2.y);
                *(char2*)(g_ka + o1) = p1; *(char2*)(g_kb + o1) = p2;
            } else if constexpr (EPI == 1) {
                float b0v = bias[cidx], b1v = bias[cidx + 1];
                float2 h0 = make_float2(fmaxf(d00 + b0v, 0.f), fmaxf(d01 + b1v, 0.f));
                float2 h1 = make_float2(fmaxf(d10 + b0v, 0.f), fmaxf(d11 + b1v, 0.f));
                *(float2*)(g_hf + (size_t)r0 * S_DIM + cidx)       = h0;
                *(float2*)(g_hf + (size_t)(r0 + 8) * S_DIM + cidx) = h1;
            } else {
                float b0v = bias[cidx], b1v = bias[cidx + 1];
                float w00 = Wh[cidx],         w01 = Wh[cidx + 1];
                float w10 = Wh[S_DIM + cidx], w11 = Wh[S_DIM + cidx + 1];
                float v00 = fmaxf(d00 + b0v, 0.f), v01 = fmaxf(d01 + b1v, 0.f);
                float v10 = fmaxf(d10 + b0v, 0.f), v11 = fmaxf(d11 + b1v, 0.f);
                o0s[mt][0] = fmaf(v00, w00, fmaf(v01, w01, o0s[mt][0]));
                o1s[mt][0] = fmaf(v00, w10, fmaf(v01, w11, o1s[mt][0]));
                o0s[mt][1] = fmaf(v10, w00, fmaf(v11, w01, o0s[mt][1]));
                o1s[mt][1] = fmaf(v10, w10, fmaf(v11, w11, o1s[mt][1]));
            }
        }
    }

    if constexpr (EPI == 2) {
        #pragma unroll
        for (int mt = 0; mt < 2; ++mt)
            #pragma unroll
            for (int rh = 0; rh < 2; ++rh) {
                float a = o0s[mt][rh], b = o1s[mt][rh];
                a += __shfl_xor_sync(0xffffffffu, a, 1);
                a += __shfl_xor_sync(0xffffffffu, a, 2);
                b += __shfl_xor_sync(0xffffffffu, b, 1);
                b += __shfl_xor_sync(0xffffffffu, b, 2);
                o0s[mt][rh] = a; o1s[mt][rh] = b;
            }
        if (tg == 0) {
            int slot = blockIdx.x * 4 + warp_n;   // 0..31
            #pragma unroll
            for (int mt = 0; mt < 2; ++mt)
                #pragma unroll
                for (int rh = 0; rh < 2; ++rh) {
                    int row = rowBase + warp_m * 32 + mt * 16 + g + rh * 8;
                    size_t base = ((size_t)slot * B_ROWS + row) * 2;
                    g_part[base]     = o0s[mt][rh];
                    g_part[base + 1] = o1s[mt][rh];
                }
        }
    }
}

// ============================================================================
// Head reduction
// ============================================================================
__global__ void head_final(const float* __restrict__ bh, float* __restrict__ out) {
    int i = blockIdx.x * blockDim.x + threadIdx.x;
    if (i < B_ROWS * 2) {
        float s = bh[i & 1];
        #pragma unroll
        for (int t = 0; t < 32; ++t) s += g_part[(size_t)t * B_ROWS * 2 + i];
        out[i] = s;
    }
}

// ============================================================================
// Launcher — GEMMs at launch indices 3 and 4 (ncu capture window)
// ============================================================================
extern "C" void kernel_launch(void* const* d_in, const int* in_sizes, int n_in,
                              void* d_out, int out_size) {
    (void)in_sizes; (void)n_in; (void)out_size;
    const float* x  = (const float*)d_in[0];
    const float* sv = (const float*)d_in[1];
    const float* W1 = (const float*)d_in[2];
    const float* b1 = (const float*)d_in[3];
    const float* W2 = (const float*)d_in[4];
    const float* b2 = (const float*)d_in[5];
    const float* Wh = (const float*)d_in[6];
    const float* bh = (const float*)d_in[7];
    float* out = (float*)d_out;

    static int8_t *xa, *xb, *sva, *svb, *w1a, *w1b, *w2a, *w2b, *ka, *kb, *ha, *hb;
    static float *hf, *xs, *svs, *w1s, *w2s, *hs, *xn, *svn;
    static bool got = false;
    if (!got) {
        cudaGetSymbolAddress((void**)&xa,  g_xa);  cudaGetSymbolAddress((void**)&xb,  g_xb);
        cudaGetSymbolAddress((void**)&sva, g_sva); cudaGetSymbolAddress((void**)&svb, g_svb);
        cudaGetSymbolAddress((void**)&w1a, g_w1a); cudaGetSymbolAddress((void**)&w1b, g_w1b);
        cudaGetSymbolAddress((void**)&w2a, g_w2a); cudaGetSymbolAddress((void**)&w2b, g_w2b);
        cudaGetSymbolAddress((void**)&ka,  g_ka);  cudaGetSymbolAddress((void**)&kb,  g_kb);
        cudaGetSymbolAddress((void**)&ha,  g_ha);  cudaGetSymbolAddress((void**)&hb,  g_hb);
        cudaGetSymbolAddress((void**)&hf,  g_hf);
        cudaGetSymbolAddress((void**)&xs,  g_xs);  cudaGetSymbolAddress((void**)&svs, g_svs);
        cudaGetSymbolAddress((void**)&w1s, g_w1s); cudaGetSymbolAddress((void**)&w2s, g_w2s);
        cudaGetSymbolAddress((void**)&hs,  g_hs);
        cudaGetSymbolAddress((void**)&xn,  g_xn);  cudaGetSymbolAddress((void**)&svn, g_svn);
        cudaFuncSetAttribute((const void*)gemm_i8<FEAT, 0>,
                             cudaFuncAttributeMaxDynamicSharedMemorySize, SMEM_TOTAL);
        cudaFuncSetAttribute((const void*)gemm_i8<S_DIM, 1>,
                             cudaFuncAttributeMaxDynamicSharedMemorySize, SMEM_TOTAL);
        cudaFuncSetAttribute((const void*)gemm_i8<S_DIM, 2>,
                             cudaFuncAttributeMaxDynamicSharedMemorySize, SMEM_TOTAL);
        got = true;
    }

    dim3 grid(S_DIM / BN, B_ROWS / BM);   // (8, 1024)

    // idx 0-2: quantize x (+norm), sv (+norm), W1
    quant_rows<FEAT, true ><<<B_ROWS / 8, 256>>>(x,  xa,  xb,  xs,  xn);
    quant_rows<FEAT, true ><<<S_DIM  / 8, 256>>>(sv, sva, svb, svs, svn);
    quant_rows<S_DIM, false><<<S_DIM / 8, 256>>>(W1, w1a, w1b, w1s, nullptr);
    // idx 3: GEMM1 (RBF features, writes int8 k directly, scale 1)
    gemm_i8<FEAT, 0><<<grid, NTH, SMEM_TOTAL>>>(xa, xb, sva, svb, xs, svs, nullptr, nullptr);
    // idx 4: GEMM2 (hidden1, fp32 out)
    gemm_i8<S_DIM, 1><<<grid, NTH, SMEM_TOTAL>>>(ka, kb, w1a, w1b, nullptr, w1s, b1, nullptr);
    // idx 5-6: quantize W2, requantize h (row max)
    quant_rows<S_DIM, false><<<S_DIM / 8, 256>>>(W2, w2a, w2b, w2s, nullptr);
    quant_rows<S_DIM, false><<<B_ROWS / 8, 256>>>(hf, ha, hb, hs, nullptr);
    // idx 7: GEMM3 (hidden2 + head partials)
    gemm_i8<S_DIM, 2><<<grid, NTH, SMEM_TOTAL>>>(ha, hb, w2a, w2b, hs, w2s, b2, Wh);
    // idx 8: head reduction
    head_final<<<(B_ROWS * 2 + 255) / 256, 256>>>(bh, out);
}

// round 9
// speedup vs baseline: 1.7838x; 1.0079x over previous
#include <cuda_runtime.h>
#include <cstdint>

// ============================================================================
// Problem constants
// ============================================================================
#define GAMMA_F 0.00390625f

constexpr int B_ROWS = 65536;
constexpr int FEAT   = 256;
constexpr int S_DIM  = 1024;

// GEMM tiling: CTA 64x128, K-chunk 128 (int8), 8 warps of 32x32, 2 CTAs/SM
constexpr int BM  = 64;
constexpr int BN  = 128;
constexpr int BK  = 128;
constexpr int NTH = 256;

constexpr int ROWB    = BK + 16;           // 144 bytes per row
constexpr int A_PLANE = BM * ROWB;         // 9216
constexpr int B_PLANE = BN * ROWB;         // 18432
constexpr int OFF_A1  = 0;
constexpr int OFF_A2  = A_PLANE;
constexpr int OFF_B1  = 2 * A_PLANE;
constexpr int OFF_B2  = 2 * A_PLANE + B_PLANE;
constexpr int STAGE   = 2 * A_PLANE + 2 * B_PLANE;   // 55296
constexpr int SMEM_TOTAL = 2 * STAGE;                // 110592 (2 CTAs/SM)

constexpr float INV254 = 1.0f / 254.0f;
constexpr float INVQ   = 1.0f / 16129.0f;   // 1/127^2
constexpr float H_SCALE = 4.0f;             // fixed quant scale for hidden h

// ============================================================================
// Device scratch (__device__ globals: alloc-free rule)
// ============================================================================
__device__ __align__(16) int8_t g_xa [(size_t)B_ROWS * FEAT];
__device__ __align__(16) int8_t g_xb [(size_t)B_ROWS * FEAT];
__device__ __align__(16) int8_t g_sva[(size_t)S_DIM * FEAT];
__device__ __align__(16) int8_t g_svb[(size_t)S_DIM * FEAT];
__device__ __align__(16) int8_t g_w1a[(size_t)S_DIM * S_DIM];
__device__ __align__(16) int8_t g_w1b[(size_t)S_DIM * S_DIM];
__device__ __align__(16) int8_t g_w2a[(size_t)S_DIM * S_DIM];
__device__ __align__(16) int8_t g_w2b[(size_t)S_DIM * S_DIM];
__device__ __align__(16) int8_t g_ka [(size_t)B_ROWS * S_DIM];
__device__ __align__(16) int8_t g_kb [(size_t)B_ROWS * S_DIM];
__device__ __align__(16) int8_t g_ha [(size_t)B_ROWS * S_DIM];
__device__ __align__(16) int8_t g_hb [(size_t)B_ROWS * S_DIM];
__device__ float g_xs [B_ROWS];
__device__ float g_svs[S_DIM];
__device__ float g_w1s[S_DIM];
__device__ float g_w2s[S_DIM];
__device__ float g_xn [B_ROWS];
__device__ float g_svn[S_DIM];
__device__ float g_part[32 * B_ROWS * 2];

// ============================================================================
// PTX helpers
// ============================================================================
__device__ __forceinline__ uint32_t smem_u32(const void* p) {
    uint32_t a;
    asm("{ .reg .u64 t; cvta.to.shared.u64 t, %1; cvt.u32.u64 %0, t; }"
        : "=r"(a) : "l"(p));
    return a;
}

__device__ __forceinline__ void cp16(uint32_t s, const void* g) {
    asm volatile("cp.async.cg.shared.global [%0], [%1], 16;"
                 :: "r"(s), "l"((unsigned long long)(uintptr_t)g) : "memory");
}
#define CP_COMMIT()  asm volatile("cp.async.commit_group;" ::: "memory")
#define CP_WAIT0()   asm volatile("cp.async.wait_group 0;" ::: "memory")

__device__ __forceinline__ void ldm_x4(uint32_t* r, uint32_t saddr) {
    asm volatile("ldmatrix.sync.aligned.m8n8.x4.shared.b16 {%0,%1,%2,%3}, [%4];"
                 : "=r"(r[0]), "=r"(r[1]), "=r"(r[2]), "=r"(r[3]) : "r"(saddr));
}

#define IMMA(C, A, B0, B1)                                                     \
    asm volatile(                                                              \
        "mma.sync.aligned.m16n8k32.row.col.s32.s8.s8.s32 "                     \
        "{%0,%1,%2,%3}, {%4,%5,%6,%7}, {%8,%9}, {%0,%1,%2,%3};"                \
        : "+r"((C)[0]), "+r"((C)[1]), "+r"((C)[2]), "+r"((C)[3])               \
        : "r"((A)[0]), "r"((A)[1]), "r"((A)[2]), "r"((A)[3]),                  \
          "r"(B0), "r"(B1))

// fp32 -> 2-slice int8 (inv = 127/scale), clamped
__device__ __forceinline__ void qpair(float v, float inv, int8_t& o1, int8_t& o2) {
    float q = fminf(fmaxf(v * inv, -127.0f), 127.0f);
    float R = rintf(q);
    o1 = (int8_t)(int)R;
    o2 = (int8_t)(int)rintf((q - R) * 254.0f);
}

// ============================================================================
// Row-wise 2-slice quantizer (warp per row)
// ============================================================================
template <int COLS, bool NORM>
__global__ void quant_rows(const float* __restrict__ src,
                           int8_t* __restrict__ q1, int8_t* __restrict__ q2,
                           float* __restrict__ sOut, float* __restrict__ nrm) {
    int row  = blockIdx.x * 8 + (threadIdx.x >> 5);
    int lane = threadIdx.x & 31;
    const float4* s4 = (const float4*)(src + (size_t)row * COLS);
    float4 vb[COLS / 128];
    float mx = 0.f, ss = 0.f;
    #pragma unroll
    for (int i = 0; i < COLS / 128; ++i) {
        float4 v = s4[i * 32 + lane];
        vb[i] = v;
        mx = fmaxf(mx, fmaxf(fmaxf(fabsf(v.x), fabsf(v.y)),
                             fmaxf(fabsf(v.z), fabsf(v.w))));
        if (NORM)
            ss = fmaf(v.x, v.x, fmaf(v.y, v.y, fmaf(v.z, v.z, fmaf(v.w, v.w, ss))));
    }
    #pragma unroll
    for (int o = 16; o; o >>= 1) {
        mx = fmaxf(mx, __shfl_xor_sync(0xffffffffu, mx, o));
        if (NORM) ss += __shfl_xor_sync(0xffffffffu, ss, o);
    }
    float s = mx > 0.f ? mx : 1.0f;
    if (lane == 0) {
        sOut[row] = s;
        if (NORM) nrm[row] = ss;
    }
    float inv = 127.0f / s;
    #pragma unroll
    for (int i = 0; i < COLS / 128; ++i) {
        char4 c1, c2;
        qpair(vb[i].x, inv, (int8_t&)c1.x, (int8_t&)c2.x);
        qpair(vb[i].y, inv, (int8_t&)c1.y, (int8_t&)c2.y);
        qpair(vb[i].z, inv, (int8_t&)c1.z, (int8_t&)c2.z);
        qpair(vb[i].w, inv, (int8_t&)c1.w, (int8_t&)c2.w);
        size_t o = (size_t)row * COLS + i * 128 + lane * 4;
        *(char4*)(q1 + o) = c1;
        *(char4*)(q2 + o) = c2;
    }
}

// ============================================================================
// Int8 2-slice GEMM.  D[m,n] = sum_k A[m,k] * B[n,k]
//  dot = (C1 + Cx/254) * sA*sB/127^2,  C1 = A1B1, Cx = A1B2 + A2B1
//  EPI 0: k = exp(g*(2*dot - xn - svn)) -> g_ka/g_kb (scale 1)
//  EPI 1: h = relu(dot + b1)            -> g_ha/g_hb (fixed scale H_SCALE)
//  EPI 2: v = relu(dot + b2); head partials -> g_part
// ============================================================================
template <int KTOT, int EPI>
__global__ void __launch_bounds__(NTH, 2)
gemm_i8(const int8_t* __restrict__ A1p, const int8_t* __restrict__ A2p,
        const int8_t* __restrict__ B1p, const int8_t* __restrict__ B2p,
        const float* __restrict__ sA, float sAc, const float* __restrict__ sB,
        const float* __restrict__ bias, const float* __restrict__ Wh) {
    extern __shared__ char smem[];
    const uint32_t sb0 = smem_u32(smem);

    const int tid    = threadIdx.x;
    const int wid    = tid >> 5;
    const int lane   = tid & 31;
    const int g      = lane >> 2;
    const int tg     = lane & 3;
    const int warp_m = wid & 1;         // 0..1  (32-row halves)
    const int warp_n = wid >> 1;        // 0..3  (32-col slices)

    const int rowBase = blockIdx.y * BM;
    const int colBase = blockIdx.x * BN;
    constexpr int NCHUNK = KTOT / BK;

    const int a_row = warp_m * 32 + (lane & 7) + ((lane >> 3) & 1) * 8;
    const int a_kby = (lane >> 4) * 16;
    const int b_row = warp_n * 32 + (lane & 7) + (lane >> 4) * 8;
    const int b_kby = ((lane >> 3) & 1) * 16;

    auto load_stage = [&](int c) {
        uint32_t s0 = sb0 + (c & 1) * STAGE;
        const int kc = c * BK;
        #pragma unroll
        for (int u = tid; u < BM * 8; u += NTH) {
            int row = u >> 3, seg = u & 7;
            size_t go = (size_t)(rowBase + row) * KTOT + kc + seg * 16;
            cp16(s0 + OFF_A1 + row * ROWB + seg * 16, A1p + go);
            cp16(s0 + OFF_A2 + row * ROWB + seg * 16, A2p + go);
        }
        #pragma unroll
        for (int u = tid; u < BN * 8; u += NTH) {
            int row = u >> 3, seg = u & 7;
            size_t go = (size_t)(colBase + row) * KTOT + kc + seg * 16;
            cp16(s0 + OFF_B1 + row * ROWB + seg * 16, B1p + go);
            cp16(s0 + OFF_B2 + row * ROWB + seg * 16, B2p + go);
        }
        CP_COMMIT();
    };

    int C1[2][4][4], Cx[2][4][4];
    #pragma unroll
    for (int mt = 0; mt < 2; ++mt)
        #pragma unroll
        for (int nt = 0; nt < 4; ++nt)
            #pragma unroll
            for (int i = 0; i < 4; ++i) { C1[mt][nt][i] = 0; Cx[mt][nt][i] = 0; }

    load_stage(0);

    for (int c = 0; c < NCHUNK; ++c) {
        CP_WAIT0();           // own-thread loads of stage c complete
        __syncthreads();      // stage c visible to all; all warps past compute(c-1)
        if (c + 1 < NCHUNK) load_stage(c + 1);   // overlaps compute below

        const uint32_t sb = sb0 + (c & 1) * STAGE;

        #pragma unroll
        for (int kk = 0; kk < BK / 32; ++kk) {
            const uint32_t ab = sb + (uint32_t)(a_row * ROWB + kk * 32 + a_kby);
            const uint32_t bb = sb + (uint32_t)(b_row * ROWB + kk * 32 + b_kby);

            uint32_t aF[2][4], bF[2][4], bG[2][4];

            // All slice-1 + B2 loads up front (max latency cover)
            #pragma unroll
            for (int mt = 0; mt < 2; ++mt) ldm_x4(aF[mt], ab + OFF_A1 + mt * 16 * ROWB);
            #pragma unroll
            for (int ne = 0; ne < 2; ++ne) ldm_x4(bF[ne], bb + OFF_B1 + ne * 16 * ROWB);
            #pragma unroll
            for (int ne = 0; ne < 2; ++ne) ldm_x4(bG[ne], bb + OFF_B2 + ne * 16 * ROWB);

            // pass 1: A1*B1 -> C1
            #pragma unroll
            for (int mt = 0; mt < 2; ++mt)
                #pragma unroll
                for (int nt = 0; nt < 4; ++nt) {
                    const int ne = nt >> 1, h2 = (nt & 1) * 2;
                    IMMA(C1[mt][nt], aF[mt], bF[ne][h2], bF[ne][h2 + 1]);
                }
            // pass 2: A1*B2 -> Cx
            #pragma unroll
            for (int mt = 0; mt < 2; ++mt)
                #pragma unroll
                for (int nt = 0; nt < 4; ++nt) {
                    const int ne = nt >> 1, h2 = (nt & 1) * 2;
                    IMMA(Cx[mt][nt], aF[mt], bG[ne][h2], bG[ne][h2 + 1]);
                }
            // A2 loads (reuse aF regs), then pass 3: A2*B1 -> Cx
            #pragma unroll
            for (int mt = 0; mt < 2; ++mt) ldm_x4(aF[mt], ab + OFF_A2 + mt * 16 * ROWB);
            #pragma unroll
            for (int mt = 0; mt < 2; ++mt)
                #pragma unroll
                for (int nt = 0; nt < 4; ++nt) {
                    const int ne = nt >> 1, h2 = (nt & 1) * 2;
                    IMMA(Cx[mt][nt], aF[mt], bF[ne][h2], bF[ne][h2 + 1]);
                }
        }
        // no trailing __syncthreads: next iteration's top barrier provides the
        // ordering (load_stage(c+2) is issued only after it), so warps de-lockstep.
    }

    // ---------------- Epilogue ----------------
    float o0s[2][2], o1s[2][2];
    if constexpr (EPI == 2) {
        #pragma unroll
        for (int mt = 0; mt < 2; ++mt) { o0s[mt][0] = o0s[mt][1] = 0.f;
                                         o1s[mt][0] = o1s[mt][1] = 0.f; }
    }

    #pragma unroll
    for (int mt = 0; mt < 2; ++mt) {
        const int r0 = rowBase + warp_m * 32 + mt * 16 + g;
        const float sa0 = sA ? sA[r0] : sAc;
        const float sa1 = sA ? sA[r0 + 8] : sAc;
        float xn0 = 0.f, xn1 = 0.f;
        if (EPI == 0) { xn0 = g_xn[r0]; xn1 = g_xn[r0 + 8]; }

        #pragma unroll
        for (int nt = 0; nt < 4; ++nt) {
            const int cidx = colBase + warp_n * 32 + nt * 8 + 2 * tg;
            const float q0 = sB[cidx] * INVQ, q1 = sB[cidx + 1] * INVQ;
            float d00 = ((float)C1[mt][nt][0] + (float)Cx[mt][nt][0] * INV254) * (sa0 * q0);
            float d01 = ((float)C1[mt][nt][1] + (float)Cx[mt][nt][1] * INV254) * (sa0 * q1);
            float d10 = ((float)C1[mt][nt][2] + (float)Cx[mt][nt][2] * INV254) * (sa1 * q0);
            float d11 = ((float)C1[mt][nt][3] + (float)Cx[mt][nt][3] * INV254) * (sa1 * q1);

            if constexpr (EPI == 0) {
                float sn0 = g_svn[cidx], sn1 = g_svn[cidx + 1];
                float k00 = __expf(GAMMA_F * (2.f * d00 - xn0 - sn0));
                float k01 = __expf(GAMMA_F * (2.f * d01 - xn0 - sn1));
                float k10 = __expf(GAMMA_F * (2.f * d10 - xn1 - sn0));
                float k11 = __expf(GAMMA_F * (2.f * d11 - xn1 - sn1));
                char2 p1, p2;
                size_t o0 = (size_t)r0 * S_DIM + cidx;
                size_t o1 = (size_t)(r0 + 8) * S_DIM + cidx;
                qpair(k00, 127.0f, (int8_t&)p1.x, (int8_t&)p2.x);
                qpair(k01, 127.0f, (int8_t&)p1.y, (int8_t&)p2.y);
                *(char2*)(g_ka + o0) = p1; *(char2*)(g_kb + o0) = p2;
                qpair(k10, 127.0f, (int8_t&)p1.x, (int8_t&)p2.x);
                qpair(k11, 127.0f, (int8_t&)p1.y, (int8_t&)p2.y);
                *(char2*)(g_ka + o1) = p1; *(char2*)(g_kb + o1) = p2;
            } else if constexpr (EPI == 1) {
                const float invh = 127.0f / H_SCALE;
                float b0v = bias[cidx], b1v = bias[cidx + 1];
                float h00 = fmaxf(d00 + b0v, 0.f), h01 = fmaxf(d01 + b1v, 0.f);
                float h10 = fmaxf(d10 + b0v, 0.f), h11 = fmaxf(d11 + b1v, 0.f);
                char2 p1, p2;
                size_t o0 = (size_t)r0 * S_DIM + cidx;
                size_t o1 = (size_t)(r0 + 8) * S_DIM + cidx;
                qpair(h00, invh, (int8_t&)p1.x, (int8_t&)p2.x);
                qpair(h01, invh, (int8_t&)p1.y, (int8_t&)p2.y);
                *(char2*)(g_ha + o0) = p1; *(char2*)(g_hb + o0) = p2;
                qpair(h10, invh, (int8_t&)p1.x, (int8_t&)p2.x);
                qpair(h11, invh, (int8_t&)p1.y, (int8_t&)p2.y);
                *(char2*)(g_ha + o1) = p1; *(char2*)(g_hb + o1) = p2;
            } else {
                float b0v = bias[cidx], b1v = bias[cidx + 1];
                float w00 = Wh[cidx],         w01 = Wh[cidx + 1];
                float w10 = Wh[S_DIM + cidx], w11 = Wh[S_DIM + cidx + 1];
                float v00 = fmaxf(d00 + b0v, 0.f), v01 = fmaxf(d01 + b1v, 0.f);
                float v10 = fmaxf(d10 + b0v, 0.f), v11 = fmaxf(d11 + b1v, 0.f);
                o0s[mt][0] = fmaf(v00, w00, fmaf(v01, w01, o0s[mt][0]));
                o1s[mt][0] = fmaf(v00, w10, fmaf(v01, w11, o1s[mt][0]));
                o0s[mt][1] = fmaf(v10, w00, fmaf(v11, w01, o0s[mt][1]));
                o1s[mt][1] = fmaf(v10, w10, fmaf(v11, w11, o1s[mt][1]));
            }
        }
    }

    if constexpr (EPI == 2) {
        #pragma unroll
        for (int mt = 0; mt < 2; ++mt)
            #pragma unroll
            for (int rh = 0; rh < 2; ++rh) {
                float a = o0s[mt][rh], b = o1s[mt][rh];
                a += __shfl_xor_sync(0xffffffffu, a, 1);
                a += __shfl_xor_sync(0xffffffffu, a, 2);
                b += __shfl_xor_sync(0xffffffffu, b, 1);
                b += __shfl_xor_sync(0xffffffffu, b, 2);
                o0s[mt][rh] = a; o1s[mt][rh] = b;
            }
        if (tg == 0) {
            int slot = blockIdx.x * 4 + warp_n;   // 0..31
            #pragma unroll
            for (int mt = 0; mt < 2; ++mt)
                #pragma unroll
                for (int rh = 0; rh < 2; ++rh) {
                    int row = rowBase + warp_m * 32 + mt * 16 + g + rh * 8;
                    size_t base = ((size_t)slot * B_ROWS + row) * 2;
                    g_part[base]     = o0s[mt][rh];
                    g_part[base + 1] = o1s[mt][rh];
                }
        }
    }
}

// ============================================================================
// Head reduction
// ============================================================================
__global__ void head_final(const float* __restrict__ bh, float* __restrict__ out) {
    int i = blockIdx.x * blockDim.x + threadIdx.x;
    if (i < B_ROWS * 2) {
        float s = bh[i & 1];
        #pragma unroll
        for (int t = 0; t < 32; ++t) s += g_part[(size_t)t * B_ROWS * 2 + i];
        out[i] = s;
    }
}

// ============================================================================
// Launcher — GEMM1/GEMM2 at launch indices 3/4 (ncu capture window)
// ============================================================================
extern "C" void kernel_launch(void* const* d_in, const int* in_sizes, int n_in,
                              void* d_out, int out_size) {
    (void)in_sizes; (void)n_in; (void)out_size;
    const float* x  = (const float*)d_in[0];
    const float* sv = (const float*)d_in[1];
    const float* W1 = (const float*)d_in[2];
    const float* b1 = (const float*)d_in[3];
    const float* W2 = (const float*)d_in[4];
    const float* b2 = (const float*)d_in[5];
    const float* Wh = (const float*)d_in[6];
    const float* bh = (const float*)d_in[7];
    float* out = (float*)d_out;

    static int8_t *xa, *xb, *sva, *svb, *w1a, *w1b, *w2a, *w2b, *ka, *kb, *ha, *hb;
    static float *xs, *svs, *w1s, *w2s, *xn, *svn;
    static bool got = false;
    if (!got) {
        cudaGetSymbolAddress((void**)&xa,  g_xa);  cudaGetSymbolAddress((void**)&xb,  g_xb);
        cudaGetSymbolAddress((void**)&sva, g_sva); cudaGetSymbolAddress((void**)&svb, g_svb);
        cudaGetSymbolAddress((void**)&w1a, g_w1a); cudaGetSymbolAddress((void**)&w1b, g_w1b);
        cudaGetSymbolAddress((void**)&w2a, g_w2a); cudaGetSymbolAddress((void**)&w2b, g_w2b);
        cudaGetSymbolAddress((void**)&ka,  g_ka);  cudaGetSymbolAddress((void**)&kb,  g_kb);
        cudaGetSymbolAddress((void**)&ha,  g_ha);  cudaGetSymbolAddress((void**)&hb,  g_hb);
        cudaGetSymbolAddress((void**)&xs,  g_xs);  cudaGetSymbolAddress((void**)&svs, g_svs);
        cudaGetSymbolAddress((void**)&w1s, g_w1s); cudaGetSymbolAddress((void**)&w2s, g_w2s);
        cudaGetSymbolAddress((void**)&xn,  g_xn);  cudaGetSymbolAddress((void**)&svn, g_svn);
        cudaFuncSetAttribute((const void*)gemm_i8<FEAT, 0>,
                             cudaFuncAttributeMaxDynamicSharedMemorySize, SMEM_TOTAL);
        cudaFuncSetAttribute((const void*)gemm_i8<S_DIM, 1>,
                             cudaFuncAttributeMaxDynamicSharedMemorySize, SMEM_TOTAL);
        cudaFuncSetAttribute((const void*)gemm_i8<S_DIM, 2>,
                             cudaFuncAttributeMaxDynamicSharedMemorySize, SMEM_TOTAL);
        got = true;
    }

    dim3 grid(S_DIM / BN, B_ROWS / BM);   // (8, 1024)

    // idx 0-2: quantize x (+norm), sv (+norm), W1
    quant_rows<FEAT, true ><<<B_ROWS / 8, 256>>>(x,  xa,  xb,  xs,  xn);
    quant_rows<FEAT, true ><<<S_DIM  / 8, 256>>>(sv, sva, svb, svs, svn);
    quant_rows<S_DIM, false><<<S_DIM / 8, 256>>>(W1, w1a, w1b, w1s, nullptr);
    // idx 3: GEMM1 (RBF features -> int8 k, scale 1)
    gemm_i8<FEAT, 0><<<grid, NTH, SMEM_TOTAL>>>(xa, xb, sva, svb, xs, 1.0f, svs,
                                                nullptr, nullptr);
    // idx 4: GEMM2 (hidden1 -> int8 h, fixed scale H_SCALE; fused quant)
    gemm_i8<S_DIM, 1><<<grid, NTH, SMEM_TOTAL>>>(ka, kb, w1a, w1b, nullptr, 1.0f, w1s,
                                                 b1, nullptr);
    // idx 5: quantize W2
    quant_rows<S_DIM, false><<<S_DIM / 8, 256>>>(W2, w2a, w2b, w2s, nullptr);
    // idx 6: GEMM3 (hidden2 + head partials; A-scale = H_SCALE constant)
    gemm_i8<S_DIM, 2><<<grid, NTH, SMEM_TOTAL>>>(ha, hb, w2a, w2b, nullptr, H_SCALE, w2s,
                                                 b2, Wh);
    // idx 7: head reduction
    head_final<<<(B_ROWS * 2 + 255) / 256, 256>>>(bh, out);
}